// round 8
// baseline (speedup 1.0000x reference)
#include <cuda_runtime.h>
#include <cuda_bf16.h>
#include <cstdint>

#define N_NODES 10000
#define N_EDGES 320000
#define F_IN 512
#define HID 256
#define M_PAD 10112         // 10000 rounded up to 128
#define BKT 128             // bucket capacity per node

// ---------------- device scratch (static, no allocation) ----------------
// g_pos is zero-initialized at module load; fusedU re-zeroes it after each use,
// so every kernel_launch invocation (correctness, capture, replays) sees zeros.
__device__ __align__(16) int   g_pos[N_NODES];
__device__ __align__(16) int   g_bkt[(size_t)N_NODES * BKT];   // src ids per dst
__device__ __align__(16) float g_H0[(size_t)N_NODES * HID];
__device__ __align__(16) float g_Z[N_NODES * 2];               // pre-scaled by rdeg[node]
__device__ __align__(16) __nv_bfloat16 g_Ah[(size_t)M_PAD * F_IN];
__device__ __align__(16) __nv_bfloat16 g_Al[(size_t)M_PAD * F_IN];
__device__ __align__(16) __nv_bfloat16 g_Bh[HID * F_IN];       // W1^T hi [n][k]
__device__ __align__(16) __nv_bfloat16 g_Bl[HID * F_IN];       // W1^T lo [n][k]

// ---------------- static-init stream/event resources (created pre-baseline) --------
struct ForkRes {
    cudaStream_t s = nullptr;
    cudaEvent_t e1 = nullptr, e2 = nullptr;
    bool ok = false;
    ForkRes() {
        if (cudaStreamCreateWithFlags(&s, cudaStreamNonBlocking) == cudaSuccess &&
            cudaEventCreateWithFlags(&e1, cudaEventDisableTiming) == cudaSuccess &&
            cudaEventCreateWithFlags(&e2, cudaEventDisableTiming) == cudaSuccess)
            ok = true;
    }
};
static ForkRes g_fork;

// ---------------- mma/ldmatrix/cp.async helpers (base ISA, sm_80+) ----------------
#define LDSM_X4(r0, r1, r2, r3, addr) \
    asm volatile("ldmatrix.sync.aligned.m8n8.x4.shared.b16 {%0,%1,%2,%3}, [%4];" \
        : "=r"(r0), "=r"(r1), "=r"(r2), "=r"(r3) : "r"(addr))
#define LDSM_X2(r0, r1, addr) \
    asm volatile("ldmatrix.sync.aligned.m8n8.x2.shared.b16 {%0,%1}, [%2];" \
        : "=r"(r0), "=r"(r1) : "r"(addr))
#define MMA_BF16(d0, d1, d2, d3, a0, a1, a2, a3, b0, b1) \
    asm volatile("mma.sync.aligned.m16n8k16.row.col.f32.bf16.bf16.f32 " \
        "{%0,%1,%2,%3}, {%4,%5,%6,%7}, {%8,%9}, {%0,%1,%2,%3};" \
        : "+f"(d0), "+f"(d1), "+f"(d2), "+f"(d3) \
        : "r"(a0), "r"(a1), "r"(a2), "r"(a3), "r"(b0), "r"(b1))
#define CP16(saddr, gptr) \
    asm volatile("cp.async.cg.shared.global [%0], [%1], 16;" :: "r"(saddr), "l"(gptr))
#define CP_COMMIT() asm volatile("cp.async.commit_group;" ::: "memory")
#define CP_WAIT1()  asm volatile("cp.async.wait_group 1;" ::: "memory")

// ---------------- bucket scatter ----------------
__global__ void scatter_kernel(const int* __restrict__ ei) {
    int e = blockIdx.x * blockDim.x + threadIdx.x;
    if (e >= N_EDGES) return;
    int s = ei[e];
    int d = ei[N_EDGES + e];
    int pos = atomicAdd(&g_pos[d], 1);
    if (pos < BKT) g_bkt[(size_t)d * BKT + pos] = s;
}

// ---------------- prep: bf16-split A, and transpose+split W1 ----------------
__global__ void prep_kernel(const float* __restrict__ A, const float* __restrict__ W1) {
    int tid = blockIdx.x * blockDim.x + threadIdx.x;
    if (tid < (N_NODES * F_IN) / 8) {
        int idx8 = tid * 8;
        const float* p = A + idx8;
        float4 v0 = *(const float4*)p;
        float4 v1 = *(const float4*)(p + 4);
        float vals[8] = {v0.x, v0.y, v0.z, v0.w, v1.x, v1.y, v1.z, v1.w};
        uint32_t hw[4], lw[4];
        #pragma unroll
        for (int q = 0; q < 4; q++) {
            __nv_bfloat16 h0 = __float2bfloat16_rn(vals[2 * q]);
            __nv_bfloat16 h1 = __float2bfloat16_rn(vals[2 * q + 1]);
            float r0 = vals[2 * q] - __bfloat162float(h0);
            float r1 = vals[2 * q + 1] - __bfloat162float(h1);
            __nv_bfloat16 l0 = __float2bfloat16_rn(r0);
            __nv_bfloat16 l1 = __float2bfloat16_rn(r1);
            hw[q] = (uint32_t)*(unsigned short*)&h0 | ((uint32_t)*(unsigned short*)&h1 << 16);
            lw[q] = (uint32_t)*(unsigned short*)&l0 | ((uint32_t)*(unsigned short*)&l1 << 16);
        }
        *(uint4*)(g_Ah + idx8) = make_uint4(hw[0], hw[1], hw[2], hw[3]);
        *(uint4*)(g_Al + idx8) = make_uint4(lw[0], lw[1], lw[2], lw[3]);
    }
    if (tid < (F_IN * HID) / 8) {
        int n = tid & 255;
        int kb = (tid >> 8) * 8;
        uint32_t hw[4], lw[4];
        #pragma unroll
        for (int q = 0; q < 4; q++) {
            float x0 = W1[(size_t)(kb + 2 * q) * HID + n];
            float x1 = W1[(size_t)(kb + 2 * q + 1) * HID + n];
            __nv_bfloat16 h0 = __float2bfloat16_rn(x0);
            __nv_bfloat16 h1 = __float2bfloat16_rn(x1);
            float r0 = x0 - __bfloat162float(h0);
            float r1 = x1 - __bfloat162float(h1);
            __nv_bfloat16 l0 = __float2bfloat16_rn(r0);
            __nv_bfloat16 l1 = __float2bfloat16_rn(r1);
            hw[q] = (uint32_t)*(unsigned short*)&h0 | ((uint32_t)*(unsigned short*)&h1 << 16);
            lw[q] = (uint32_t)*(unsigned short*)&l0 | ((uint32_t)*(unsigned short*)&l1 << 16);
        }
        *(uint4*)(g_Bh + (size_t)n * F_IN + kb) = make_uint4(hw[0], hw[1], hw[2], hw[3]);
        *(uint4*)(g_Bl + (size_t)n * F_IN + kb) = make_uint4(lw[0], lw[1], lw[2], lw[3]);
    }
}

// ---------------- HMMA GEMM, cp.async double-buffered ----------------
#define ROWB 80
#define STG 40960
#define S_AH 0
#define S_AL 10240
#define S_BH 20480
#define S_BL 30720

__global__ __launch_bounds__(256, 2) void gemm_mma_kernel(const float* __restrict__ bias) {
    extern __shared__ __align__(128) char sm[];
    uint32_t sbase = (uint32_t)__cvta_generic_to_shared(sm);

    const int M = N_NODES;
    int tid = threadIdx.x;
    int wid = tid >> 5;
    int lane = tid & 31;
    int wm = wid >> 2;
    int wn = wid & 3;
    int bm = blockIdx.y * 128;
    int bn = blockIdx.x * 128;

    int r0i = tid >> 2, j0 = tid & 3;
    int r1i = (tid + 256) >> 2, j1 = tid & 3;

    float acc[4][4][4];
    #pragma unroll
    for (int i = 0; i < 4; i++)
        #pragma unroll
        for (int j = 0; j < 4; j++)
            #pragma unroll
            for (int r = 0; r < 4; r++) acc[i][j][r] = 0.f;

    auto load_stage = [&](int c, int s) {
        int k0 = c * 32;
        uint32_t sb = sbase + s * STG;
        const char* gAh = (const char*)(g_Ah + (size_t)bm * F_IN + k0);
        const char* gAl = (const char*)(g_Al + (size_t)bm * F_IN + k0);
        const char* gBh = (const char*)(g_Bh + (size_t)bn * F_IN + k0);
        const char* gBl = (const char*)(g_Bl + (size_t)bn * F_IN + k0);
        {
            int r = r0i, j = j0;
            size_t go = (size_t)r * (F_IN * 2) + j * 16;
            uint32_t so = r * ROWB + j * 16;
            CP16(sb + S_AH + so, gAh + go);
            CP16(sb + S_AL + so, gAl + go);
            CP16(sb + S_BH + so, gBh + go);
            CP16(sb + S_BL + so, gBl + go);
        }
        {
            int r = r1i, j = j1;
            size_t go = (size_t)r * (F_IN * 2) + j * 16;
            uint32_t so = r * ROWB + j * 16;
            CP16(sb + S_AH + so, gAh + go);
            CP16(sb + S_AL + so, gAl + go);
            CP16(sb + S_BH + so, gBh + go);
            CP16(sb + S_BL + so, gBl + go);
        }
    };

    load_stage(0, 0);
    CP_COMMIT();

    for (int c = 0; c < 16; c++) {
        int s = c & 1;
        if (c + 1 < 16) load_stage(c + 1, (c + 1) & 1);
        CP_COMMIT();
        CP_WAIT1();
        __syncthreads();

        uint32_t stb = sbase + s * STG;
        #pragma unroll
        for (int ks = 0; ks < 2; ks++) {
            int kbyte = ks * 32;
            uint32_t bh[4][2], bl[4][2];
            #pragma unroll
            for (int na = 0; na < 4; na++) {
                uint32_t ad = stb + S_BH +
                    (uint32_t)((wn * 32 + na * 8 + (lane & 7)) * ROWB + kbyte + ((lane >> 3) & 1) * 16);
                LDSM_X2(bh[na][0], bh[na][1], ad);
                LDSM_X2(bl[na][0], bl[na][1], ad + (S_BL - S_BH));
            }
            #pragma unroll
            for (int ma = 0; ma < 4; ma++) {
                uint32_t aad = stb + S_AH +
                    (uint32_t)((wm * 64 + ma * 16 + (lane & 15)) * ROWB + kbyte + (lane >> 4) * 16);
                uint32_t ah0, ah1, ah2, ah3, al0, al1, al2, al3;
                LDSM_X4(ah0, ah1, ah2, ah3, aad);
                LDSM_X4(al0, al1, al2, al3, aad + (S_AL - S_AH));
                #pragma unroll
                for (int na = 0; na < 4; na++) {
                    MMA_BF16(acc[ma][na][0], acc[ma][na][1], acc[ma][na][2], acc[ma][na][3],
                             ah0, ah1, ah2, ah3, bh[na][0], bh[na][1]);
                    MMA_BF16(acc[ma][na][0], acc[ma][na][1], acc[ma][na][2], acc[ma][na][3],
                             ah0, ah1, ah2, ah3, bl[na][0], bl[na][1]);
                    MMA_BF16(acc[ma][na][0], acc[ma][na][1], acc[ma][na][2], acc[ma][na][3],
                             al0, al1, al2, al3, bh[na][0], bh[na][1]);
                }
            }
        }
        __syncthreads();
    }

    #pragma unroll
    for (int ma = 0; ma < 4; ma++) {
        int grow0 = bm + wm * 64 + ma * 16 + (lane >> 2);
        int grow1 = grow0 + 8;
        #pragma unroll
        for (int na = 0; na < 4; na++) {
            int col = bn + wn * 32 + na * 8 + (lane & 3) * 2;
            float2 bv = *(const float2*)(bias + col);
            if (grow0 < M) {
                float2 o = make_float2(acc[ma][na][0] + bv.x, acc[ma][na][1] + bv.y);
                *(float2*)(g_H0 + (size_t)grow0 * HID + col) = o;
            }
            if (grow1 < M) {
                float2 o = make_float2(acc[ma][na][2] + bv.x, acc[ma][na][3] + bv.y);
                *(float2*)(g_H0 + (size_t)grow1 * HID + col) = o;
            }
        }
    }
}

// ---------------- fused agg1 + relu + W2 + b2, Z pre-scaled by rdeg[node] ----------------
__global__ __launch_bounds__(256) void fusedZ_kernel(const float* __restrict__ W2,
                                                     const float* __restrict__ b2) {
    int gw = (blockIdx.x * blockDim.x + threadIdx.x) >> 5;
    int lane = threadIdx.x & 31;
    if (gw >= N_NODES) return;

    int cnt = g_pos[gw];
    float rdd = rsqrtf(fmaxf((float)cnt, 1.0f));
    if (cnt > BKT) cnt = BKT;
    const int* bkt = g_bkt + (size_t)gw * BKT;

    int cA = 4 * lane;
    int cB = 128 + 4 * lane;
    float w0a[4], w1a[4], w0b[4], w1b[4];
    #pragma unroll
    for (int j = 0; j < 4; j++) {
        w0a[j] = __ldg(&W2[(cA + j) * 2 + 0]);
        w1a[j] = __ldg(&W2[(cA + j) * 2 + 1]);
        w0b[j] = __ldg(&W2[(cB + j) * 2 + 0]);
        w1b[j] = __ldg(&W2[(cB + j) * 2 + 1]);
    }

    float acc[8] = {};
    int p = 0;
    for (; p + 4 <= cnt; p += 4) {
        int s0 = bkt[p], s1 = bkt[p + 1], s2 = bkt[p + 2], s3 = bkt[p + 3];
        float n0 = rdd * rsqrtf(fmaxf((float)g_pos[s0], 1.0f));
        float n1 = rdd * rsqrtf(fmaxf((float)g_pos[s1], 1.0f));
        float n2 = rdd * rsqrtf(fmaxf((float)g_pos[s2], 1.0f));
        float n3 = rdd * rsqrtf(fmaxf((float)g_pos[s3], 1.0f));
        const float4* r0 = (const float4*)(g_H0 + (size_t)s0 * HID);
        const float4* r1 = (const float4*)(g_H0 + (size_t)s1 * HID);
        const float4* r2 = (const float4*)(g_H0 + (size_t)s2 * HID);
        const float4* r3 = (const float4*)(g_H0 + (size_t)s3 * HID);
        float4 a0 = r0[lane], a1 = r0[lane + 32];
        float4 b0 = r1[lane], b1 = r1[lane + 32];
        float4 c0 = r2[lane], c1 = r2[lane + 32];
        float4 d0 = r3[lane], d1 = r3[lane + 32];
        acc[0] += a0.x * n0 + b0.x * n1 + c0.x * n2 + d0.x * n3;
        acc[1] += a0.y * n0 + b0.y * n1 + c0.y * n2 + d0.y * n3;
        acc[2] += a0.z * n0 + b0.z * n1 + c0.z * n2 + d0.z * n3;
        acc[3] += a0.w * n0 + b0.w * n1 + c0.w * n2 + d0.w * n3;
        acc[4] += a1.x * n0 + b1.x * n1 + c1.x * n2 + d1.x * n3;
        acc[5] += a1.y * n0 + b1.y * n1 + c1.y * n2 + d1.y * n3;
        acc[6] += a1.z * n0 + b1.z * n1 + c1.z * n2 + d1.z * n3;
        acc[7] += a1.w * n0 + b1.w * n1 + c1.w * n2 + d1.w * n3;
    }
    for (; p < cnt; p++) {
        int s0 = bkt[p];
        float n0 = rdd * rsqrtf(fmaxf((float)g_pos[s0], 1.0f));
        const float4* r0 = (const float4*)(g_H0 + (size_t)s0 * HID);
        float4 a0 = r0[lane], a1 = r0[lane + 32];
        acc[0] += a0.x * n0; acc[1] += a0.y * n0;
        acc[2] += a0.z * n0; acc[3] += a0.w * n0;
        acc[4] += a1.x * n0; acc[5] += a1.y * n0;
        acc[6] += a1.z * n0; acc[7] += a1.w * n0;
    }

    float z0 = 0.f, z1 = 0.f;
    #pragma unroll
    for (int j = 0; j < 4; j++) {
        float xa = fmaxf(acc[j], 0.f);
        float xb = fmaxf(acc[4 + j], 0.f);
        z0 += xa * w0a[j] + xb * w0b[j];
        z1 += xa * w1a[j] + xb * w1b[j];
    }
    #pragma unroll
    for (int o = 16; o; o >>= 1) {
        z0 += __shfl_down_sync(0xFFFFFFFFu, z0, o);
        z1 += __shfl_down_sync(0xFFFFFFFFu, z1, o);
    }
    if (lane == 0) {
        // pre-scale by this node's rdeg so the next aggregation needs no per-src deg
        g_Z[2 * gw + 0] = (z0 + b2[0]) * rdd;
        g_Z[2 * gw + 1] = (z1 + b2[1]) * rdd;
    }
}

// ---------------- fused agg2 + lift + projection; also re-zeroes g_pos ----------------
__global__ __launch_bounds__(256) void fusedU_kernel(const float* __restrict__ scale,
                                                     float* __restrict__ out) {
    int gw = (blockIdx.x * blockDim.x + threadIdx.x) >> 5;
    int lane = threadIdx.x & 31;
    if (gw >= N_NODES) return;

    int cnt = g_pos[gw];
    float rdd = rsqrtf(fmaxf((float)cnt, 1.0f));
    if (cnt > BKT) cnt = BKT;
    const int* bkt = g_bkt + (size_t)gw * BKT;
    __syncwarp();
    if (lane == 0) g_pos[gw] = 0;   // restore invariant for next kernel_launch call

    float u0 = 0.f, u1 = 0.f;
    for (int p = lane; p < cnt; p += 32) {
        int s = bkt[p];
        float2 z = *(const float2*)(g_Z + 2 * s);   // z already scaled by rdeg[s]
        u0 += z.x;
        u1 += z.y;
    }
    #pragma unroll
    for (int o = 16; o; o >>= 1) {
        u0 += __shfl_down_sync(0xFFFFFFFFu, u0, o);
        u1 += __shfl_down_sync(0xFFFFFFFFu, u1, o);
    }
    if (lane == 0) {
        u0 *= rdd;
        u1 *= rdd;
        float un = sqrtf(u0 * u0 + u1 * u1);
        un = fmaxf(un, 1e-15f);
        float ch = coshf(un);
        float sh = sinhf(un);
        float inv = 1.0f / (un * (1.0f + ch));
        float p0 = sh * u0 * inv;
        float p1 = sh * u1 * inv;
        float pn = fmaxf(sqrtf(p0 * p0 + p1 * p1), 1e-12f);
        const float MIN_SCALE = 2.0f * (0.999f / 3.0f);
        const float MAX_SCALE = 0.999f;
        float s = fminf(fmaxf(scale[0], MIN_SCALE), MAX_SCALE);
        p0 = p0 / pn * s;
        p1 = p1 / pn * s;
        float nrm = fmaxf(sqrtf(p0 * p0 + p1 * p1), 1e-15f);
        float maxnorm = 1.0f - 1e-15f;
        if (nrm > maxnorm) {
            p0 = p0 / nrm * maxnorm;
            p1 = p1 / nrm * maxnorm;
        }
        out[2 * gw + 0] = p0;
        out[2 * gw + 1] = p1;
    }
}

// ---------------- launch ----------------
extern "C" void kernel_launch(void* const* d_in, const int* in_sizes, int n_in,
                              void* d_out, int out_size) {
    const float* feature = (const float*)d_in[0];
    const int* ei = (const int*)d_in[1];
    const float* W1 = (const float*)d_in[2];
    const float* b1 = (const float*)d_in[3];
    const float* W2 = (const float*)d_in[4];
    const float* b2 = (const float*)d_in[5];
    const float* scale = (const float*)d_in[6];
    float* out = (float*)d_out;

    cudaFuncSetAttribute(gemm_mma_kernel,
                         cudaFuncAttributeMaxDynamicSharedMemorySize, 2 * STG);

    dim3 gemm_grid(HID / 128, (N_NODES + 127) / 128);   // (2, 79)
    int prep_blocks = ((N_NODES * F_IN / 8) + 255) / 256;

    if (g_fork.ok) {
        // fork: prep+gemm on side stream, scatter on main stream, join before fusedZ
        cudaEventRecord(g_fork.e1, 0);
        cudaStreamWaitEvent(g_fork.s, g_fork.e1, 0);
        prep_kernel<<<prep_blocks, 256, 0, g_fork.s>>>(feature, W1);
        gemm_mma_kernel<<<gemm_grid, 256, 2 * STG, g_fork.s>>>(b1);
        cudaEventRecord(g_fork.e2, g_fork.s);

        scatter_kernel<<<(N_EDGES + 255) / 256, 256>>>(ei);
        cudaStreamWaitEvent(0, g_fork.e2, 0);
    } else {
        prep_kernel<<<prep_blocks, 256>>>(feature, W1);
        gemm_mma_kernel<<<gemm_grid, 256, 2 * STG>>>(b1);
        scatter_kernel<<<(N_EDGES + 255) / 256, 256>>>(ei);
    }

    fusedZ_kernel<<<(N_NODES * 32 + 255) / 256, 256>>>(W2, b2);
    fusedU_kernel<<<(N_NODES * 32 + 255) / 256, 256>>>(scale, out);
}

// round 9
// speedup vs baseline: 1.0045x; 1.0045x over previous
#include <cuda_runtime.h>
#include <cuda_bf16.h>
#include <cuda_fp16.h>
#include <cstdint>

#define N_NODES 10000
#define N_EDGES 320000
#define F_IN 512
#define HID 256
#define M_PAD 10112         // 10000 rounded up to 128
#define BKT 128             // bucket capacity per node

// ---------------- device scratch (static, no allocation) ----------------
// g_pos is zero-initialized at module load; fusedU re-zeroes it after each use.
__device__ __align__(16) int   g_pos[N_NODES];
__device__ __align__(16) int   g_bkt[(size_t)N_NODES * BKT];   // src ids per dst
__device__ __align__(16) __half g_H0h[(size_t)N_NODES * HID];  // fp16 H0
__device__ __align__(16) float g_Z[N_NODES * 2];               // pre-scaled by rdeg[node]
__device__ __align__(16) __nv_bfloat16 g_Ah[(size_t)M_PAD * F_IN];
__device__ __align__(16) __nv_bfloat16 g_Al[(size_t)M_PAD * F_IN];
__device__ __align__(16) __nv_bfloat16 g_Bh[HID * F_IN];       // W1^T hi [n][k]
__device__ __align__(16) __nv_bfloat16 g_Bl[HID * F_IN];       // W1^T lo [n][k]

// ---------------- static-init stream/event resources ----------------
struct ForkRes {
    cudaStream_t s = nullptr;
    cudaEvent_t e1 = nullptr, e2 = nullptr;
    bool ok = false;
    ForkRes() {
        if (cudaStreamCreateWithFlags(&s, cudaStreamNonBlocking) == cudaSuccess &&
            cudaEventCreateWithFlags(&e1, cudaEventDisableTiming) == cudaSuccess &&
            cudaEventCreateWithFlags(&e2, cudaEventDisableTiming) == cudaSuccess)
            ok = true;
    }
};
static ForkRes g_fork;

// ---------------- mma/ldmatrix/cp.async helpers (base ISA, sm_80+) ----------------
#define LDSM_X4(r0, r1, r2, r3, addr) \
    asm volatile("ldmatrix.sync.aligned.m8n8.x4.shared.b16 {%0,%1,%2,%3}, [%4];" \
        : "=r"(r0), "=r"(r1), "=r"(r2), "=r"(r3) : "r"(addr))
#define LDSM_X2(r0, r1, addr) \
    asm volatile("ldmatrix.sync.aligned.m8n8.x2.shared.b16 {%0,%1}, [%2];" \
        : "=r"(r0), "=r"(r1) : "r"(addr))
#define MMA_BF16(d0, d1, d2, d3, a0, a1, a2, a3, b0, b1) \
    asm volatile("mma.sync.aligned.m16n8k16.row.col.f32.bf16.bf16.f32 " \
        "{%0,%1,%2,%3}, {%4,%5,%6,%7}, {%8,%9}, {%0,%1,%2,%3};" \
        : "+f"(d0), "+f"(d1), "+f"(d2), "+f"(d3) \
        : "r"(a0), "r"(a1), "r"(a2), "r"(a3), "r"(b0), "r"(b1))
#define CP16(saddr, gptr) \
    asm volatile("cp.async.cg.shared.global [%0], [%1], 16;" :: "r"(saddr), "l"(gptr))
#define CP_COMMIT() asm volatile("cp.async.commit_group;" ::: "memory")
#define CP_WAIT1()  asm volatile("cp.async.wait_group 1;" ::: "memory")

// ---------------- bucket scatter ----------------
__global__ void scatter_kernel(const int* __restrict__ ei) {
    int e = blockIdx.x * blockDim.x + threadIdx.x;
    if (e >= N_EDGES) return;
    int s = ei[e];
    int d = ei[N_EDGES + e];
    int pos = atomicAdd(&g_pos[d], 1);
    if (pos < BKT) g_bkt[(size_t)d * BKT + pos] = s;
}

// ---------------- prep: bf16-split A, and transpose+split W1 ----------------
__global__ void prep_kernel(const float* __restrict__ A, const float* __restrict__ W1) {
    int tid = blockIdx.x * blockDim.x + threadIdx.x;
    if (tid < (N_NODES * F_IN) / 8) {
        int idx8 = tid * 8;
        const float* p = A + idx8;
        float4 v0 = *(const float4*)p;
        float4 v1 = *(const float4*)(p + 4);
        float vals[8] = {v0.x, v0.y, v0.z, v0.w, v1.x, v1.y, v1.z, v1.w};
        uint32_t hw[4], lw[4];
        #pragma unroll
        for (int q = 0; q < 4; q++) {
            __nv_bfloat16 h0 = __float2bfloat16_rn(vals[2 * q]);
            __nv_bfloat16 h1 = __float2bfloat16_rn(vals[2 * q + 1]);
            float r0 = vals[2 * q] - __bfloat162float(h0);
            float r1 = vals[2 * q + 1] - __bfloat162float(h1);
            __nv_bfloat16 l0 = __float2bfloat16_rn(r0);
            __nv_bfloat16 l1 = __float2bfloat16_rn(r1);
            hw[q] = (uint32_t)*(unsigned short*)&h0 | ((uint32_t)*(unsigned short*)&h1 << 16);
            lw[q] = (uint32_t)*(unsigned short*)&l0 | ((uint32_t)*(unsigned short*)&l1 << 16);
        }
        *(uint4*)(g_Ah + idx8) = make_uint4(hw[0], hw[1], hw[2], hw[3]);
        *(uint4*)(g_Al + idx8) = make_uint4(lw[0], lw[1], lw[2], lw[3]);
    }
    if (tid < (F_IN * HID) / 8) {
        int n = tid & 255;
        int kb = (tid >> 8) * 8;
        uint32_t hw[4], lw[4];
        #pragma unroll
        for (int q = 0; q < 4; q++) {
            float x0 = W1[(size_t)(kb + 2 * q) * HID + n];
            float x1 = W1[(size_t)(kb + 2 * q + 1) * HID + n];
            __nv_bfloat16 h0 = __float2bfloat16_rn(x0);
            __nv_bfloat16 h1 = __float2bfloat16_rn(x1);
            float r0 = x0 - __bfloat162float(h0);
            float r1 = x1 - __bfloat162float(h1);
            __nv_bfloat16 l0 = __float2bfloat16_rn(r0);
            __nv_bfloat16 l1 = __float2bfloat16_rn(r1);
            hw[q] = (uint32_t)*(unsigned short*)&h0 | ((uint32_t)*(unsigned short*)&h1 << 16);
            lw[q] = (uint32_t)*(unsigned short*)&l0 | ((uint32_t)*(unsigned short*)&l1 << 16);
        }
        *(uint4*)(g_Bh + (size_t)n * F_IN + kb) = make_uint4(hw[0], hw[1], hw[2], hw[3]);
        *(uint4*)(g_Bl + (size_t)n * F_IN + kb) = make_uint4(lw[0], lw[1], lw[2], lw[3]);
    }
}

// ---------------- HMMA GEMM, cp.async double-buffered; fp16 epilogue ----------------
#define ROWB 80
#define STG 40960
#define S_AH 0
#define S_AL 10240
#define S_BH 20480
#define S_BL 30720

__global__ __launch_bounds__(256, 2) void gemm_mma_kernel(const float* __restrict__ bias) {
    extern __shared__ __align__(128) char sm[];
    uint32_t sbase = (uint32_t)__cvta_generic_to_shared(sm);

    const int M = N_NODES;
    int tid = threadIdx.x;
    int wid = tid >> 5;
    int lane = tid & 31;
    int wm = wid >> 2;
    int wn = wid & 3;
    int bm = blockIdx.y * 128;
    int bn = blockIdx.x * 128;

    int r0i = tid >> 2, j0 = tid & 3;
    int r1i = (tid + 256) >> 2, j1 = tid & 3;

    float acc[4][4][4];
    #pragma unroll
    for (int i = 0; i < 4; i++)
        #pragma unroll
        for (int j = 0; j < 4; j++)
            #pragma unroll
            for (int r = 0; r < 4; r++) acc[i][j][r] = 0.f;

    auto load_stage = [&](int c, int s) {
        int k0 = c * 32;
        uint32_t sb = sbase + s * STG;
        const char* gAh = (const char*)(g_Ah + (size_t)bm * F_IN + k0);
        const char* gAl = (const char*)(g_Al + (size_t)bm * F_IN + k0);
        const char* gBh = (const char*)(g_Bh + (size_t)bn * F_IN + k0);
        const char* gBl = (const char*)(g_Bl + (size_t)bn * F_IN + k0);
        {
            int r = r0i, j = j0;
            size_t go = (size_t)r * (F_IN * 2) + j * 16;
            uint32_t so = r * ROWB + j * 16;
            CP16(sb + S_AH + so, gAh + go);
            CP16(sb + S_AL + so, gAl + go);
            CP16(sb + S_BH + so, gBh + go);
            CP16(sb + S_BL + so, gBl + go);
        }
        {
            int r = r1i, j = j1;
            size_t go = (size_t)r * (F_IN * 2) + j * 16;
            uint32_t so = r * ROWB + j * 16;
            CP16(sb + S_AH + so, gAh + go);
            CP16(sb + S_AL + so, gAl + go);
            CP16(sb + S_BH + so, gBh + go);
            CP16(sb + S_BL + so, gBl + go);
        }
    };

    load_stage(0, 0);
    CP_COMMIT();

    for (int c = 0; c < 16; c++) {
        int s = c & 1;
        if (c + 1 < 16) load_stage(c + 1, (c + 1) & 1);
        CP_COMMIT();
        CP_WAIT1();
        __syncthreads();

        uint32_t stb = sbase + s * STG;
        #pragma unroll
        for (int ks = 0; ks < 2; ks++) {
            int kbyte = ks * 32;
            uint32_t bh[4][2], bl[4][2];
            #pragma unroll
            for (int na = 0; na < 4; na++) {
                uint32_t ad = stb + S_BH +
                    (uint32_t)((wn * 32 + na * 8 + (lane & 7)) * ROWB + kbyte + ((lane >> 3) & 1) * 16);
                LDSM_X2(bh[na][0], bh[na][1], ad);
                LDSM_X2(bl[na][0], bl[na][1], ad + (S_BL - S_BH));
            }
            #pragma unroll
            for (int ma = 0; ma < 4; ma++) {
                uint32_t aad = stb + S_AH +
                    (uint32_t)((wm * 64 + ma * 16 + (lane & 15)) * ROWB + kbyte + (lane >> 4) * 16);
                uint32_t ah0, ah1, ah2, ah3, al0, al1, al2, al3;
                LDSM_X4(ah0, ah1, ah2, ah3, aad);
                LDSM_X4(al0, al1, al2, al3, aad + (S_AL - S_AH));
                #pragma unroll
                for (int na = 0; na < 4; na++) {
                    MMA_BF16(acc[ma][na][0], acc[ma][na][1], acc[ma][na][2], acc[ma][na][3],
                             ah0, ah1, ah2, ah3, bh[na][0], bh[na][1]);
                    MMA_BF16(acc[ma][na][0], acc[ma][na][1], acc[ma][na][2], acc[ma][na][3],
                             ah0, ah1, ah2, ah3, bl[na][0], bl[na][1]);
                    MMA_BF16(acc[ma][na][0], acc[ma][na][1], acc[ma][na][2], acc[ma][na][3],
                             al0, al1, al2, al3, bh[na][0], bh[na][1]);
                }
            }
        }
        __syncthreads();
    }

    // epilogue: add bias, store fp16
    #pragma unroll
    for (int ma = 0; ma < 4; ma++) {
        int grow0 = bm + wm * 64 + ma * 16 + (lane >> 2);
        int grow1 = grow0 + 8;
        #pragma unroll
        for (int na = 0; na < 4; na++) {
            int col = bn + wn * 32 + na * 8 + (lane & 3) * 2;
            float2 bv = *(const float2*)(bias + col);
            if (grow0 < M) {
                __half2 o = __floats2half2_rn(acc[ma][na][0] + bv.x, acc[ma][na][1] + bv.y);
                *(__half2*)(g_H0h + (size_t)grow0 * HID + col) = o;
            }
            if (grow1 < M) {
                __half2 o = __floats2half2_rn(acc[ma][na][2] + bv.x, acc[ma][na][3] + bv.y);
                *(__half2*)(g_H0h + (size_t)grow1 * HID + col) = o;
            }
        }
    }
}

// ---------------- fused agg1 + relu + W2 + b2 (fp16 gather), Z pre-scaled ----------------
__global__ __launch_bounds__(256) void fusedZ_kernel(const float* __restrict__ W2,
                                                     const float* __restrict__ b2) {
    int gw = (blockIdx.x * blockDim.x + threadIdx.x) >> 5;
    int lane = threadIdx.x & 31;
    if (gw >= N_NODES) return;

    int cnt = g_pos[gw];
    float rdd = rsqrtf(fmaxf((float)cnt, 1.0f));
    if (cnt > BKT) cnt = BKT;
    const int* bkt = g_bkt + (size_t)gw * BKT;

    // lane owns channels [8*lane, 8*lane+8)
    int c0 = 8 * lane;
    float w0[8], w1[8];
    #pragma unroll
    for (int j = 0; j < 8; j++) {
        w0[j] = __ldg(&W2[(c0 + j) * 2 + 0]);
        w1[j] = __ldg(&W2[(c0 + j) * 2 + 1]);
    }

    float acc[8] = {};
    int p = 0;
    for (; p + 4 <= cnt; p += 4) {
        int s0 = bkt[p], s1 = bkt[p + 1], s2 = bkt[p + 2], s3 = bkt[p + 3];
        float n0 = rdd * rsqrtf(fmaxf((float)g_pos[s0], 1.0f));
        float n1 = rdd * rsqrtf(fmaxf((float)g_pos[s1], 1.0f));
        float n2 = rdd * rsqrtf(fmaxf((float)g_pos[s2], 1.0f));
        float n3 = rdd * rsqrtf(fmaxf((float)g_pos[s3], 1.0f));
        uint4 v0 = ((const uint4*)(g_H0h + (size_t)s0 * HID))[lane];
        uint4 v1 = ((const uint4*)(g_H0h + (size_t)s1 * HID))[lane];
        uint4 v2 = ((const uint4*)(g_H0h + (size_t)s2 * HID))[lane];
        uint4 v3 = ((const uint4*)(g_H0h + (size_t)s3 * HID))[lane];
        const uint32_t* w0p = &v0.x;
        const uint32_t* w1p = &v1.x;
        const uint32_t* w2p = &v2.x;
        const uint32_t* w3p = &v3.x;
        #pragma unroll
        for (int q = 0; q < 4; q++) {
            float2 f0 = __half22float2(*(const __half2*)&w0p[q]);
            float2 f1 = __half22float2(*(const __half2*)&w1p[q]);
            float2 f2 = __half22float2(*(const __half2*)&w2p[q]);
            float2 f3 = __half22float2(*(const __half2*)&w3p[q]);
            acc[2 * q + 0] += f0.x * n0 + f1.x * n1 + f2.x * n2 + f3.x * n3;
            acc[2 * q + 1] += f0.y * n0 + f1.y * n1 + f2.y * n2 + f3.y * n3;
        }
    }
    for (; p < cnt; p++) {
        int s0 = bkt[p];
        float n0 = rdd * rsqrtf(fmaxf((float)g_pos[s0], 1.0f));
        uint4 v0 = ((const uint4*)(g_H0h + (size_t)s0 * HID))[lane];
        const uint32_t* w0p = &v0.x;
        #pragma unroll
        for (int q = 0; q < 4; q++) {
            float2 f0 = __half22float2(*(const __half2*)&w0p[q]);
            acc[2 * q + 0] += f0.x * n0;
            acc[2 * q + 1] += f0.y * n0;
        }
    }

    float z0 = 0.f, z1 = 0.f;
    #pragma unroll
    for (int j = 0; j < 8; j++) {
        float x = fmaxf(acc[j], 0.f);
        z0 += x * w0[j];
        z1 += x * w1[j];
    }
    #pragma unroll
    for (int o = 16; o; o >>= 1) {
        z0 += __shfl_down_sync(0xFFFFFFFFu, z0, o);
        z1 += __shfl_down_sync(0xFFFFFFFFu, z1, o);
    }
    if (lane == 0) {
        g_Z[2 * gw + 0] = (z0 + b2[0]) * rdd;
        g_Z[2 * gw + 1] = (z1 + b2[1]) * rdd;
    }
}

// ---------------- fused agg2 + lift + projection; also re-zeroes g_pos ----------------
__global__ __launch_bounds__(256) void fusedU_kernel(const float* __restrict__ scale,
                                                     float* __restrict__ out) {
    int gw = (blockIdx.x * blockDim.x + threadIdx.x) >> 5;
    int lane = threadIdx.x & 31;
    if (gw >= N_NODES) return;

    int cnt = g_pos[gw];
    float rdd = rsqrtf(fmaxf((float)cnt, 1.0f));
    if (cnt > BKT) cnt = BKT;
    const int* bkt = g_bkt + (size_t)gw * BKT;
    __syncwarp();
    if (lane == 0) g_pos[gw] = 0;   // restore invariant for next call

    float u0 = 0.f, u1 = 0.f;
    for (int p = lane; p < cnt; p += 32) {
        int s = bkt[p];
        float2 z = *(const float2*)(g_Z + 2 * s);
        u0 += z.x;
        u1 += z.y;
    }
    #pragma unroll
    for (int o = 16; o; o >>= 1) {
        u0 += __shfl_down_sync(0xFFFFFFFFu, u0, o);
        u1 += __shfl_down_sync(0xFFFFFFFFu, u1, o);
    }
    if (lane == 0) {
        u0 *= rdd;
        u1 *= rdd;
        float un = sqrtf(u0 * u0 + u1 * u1);
        un = fmaxf(un, 1e-15f);
        float ch = coshf(un);
        float sh = sinhf(un);
        float inv = 1.0f / (un * (1.0f + ch));
        float p0 = sh * u0 * inv;
        float p1 = sh * u1 * inv;
        float pn = fmaxf(sqrtf(p0 * p0 + p1 * p1), 1e-12f);
        const float MIN_SCALE = 2.0f * (0.999f / 3.0f);
        const float MAX_SCALE = 0.999f;
        float s = fminf(fmaxf(scale[0], MIN_SCALE), MAX_SCALE);
        p0 = p0 / pn * s;
        p1 = p1 / pn * s;
        float nrm = fmaxf(sqrtf(p0 * p0 + p1 * p1), 1e-15f);
        float maxnorm = 1.0f - 1e-15f;
        if (nrm > maxnorm) {
            p0 = p0 / nrm * maxnorm;
            p1 = p1 / nrm * maxnorm;
        }
        out[2 * gw + 0] = p0;
        out[2 * gw + 1] = p1;
    }
}

// ---------------- launch ----------------
extern "C" void kernel_launch(void* const* d_in, const int* in_sizes, int n_in,
                              void* d_out, int out_size) {
    const float* feature = (const float*)d_in[0];
    const int* ei = (const int*)d_in[1];
    const float* W1 = (const float*)d_in[2];
    const float* b1 = (const float*)d_in[3];
    const float* W2 = (const float*)d_in[4];
    const float* b2 = (const float*)d_in[5];
    const float* scale = (const float*)d_in[6];
    float* out = (float*)d_out;

    cudaFuncSetAttribute(gemm_mma_kernel,
                         cudaFuncAttributeMaxDynamicSharedMemorySize, 2 * STG);

    dim3 gemm_grid(HID / 128, (N_NODES + 127) / 128);   // (2, 79)
    int prep_blocks = ((N_NODES * F_IN / 8) + 255) / 256;

    if (g_fork.ok) {
        cudaEventRecord(g_fork.e1, 0);
        cudaStreamWaitEvent(g_fork.s, g_fork.e1, 0);
        prep_kernel<<<prep_blocks, 256, 0, g_fork.s>>>(feature, W1);
        gemm_mma_kernel<<<gemm_grid, 256, 2 * STG, g_fork.s>>>(b1);
        cudaEventRecord(g_fork.e2, g_fork.s);

        scatter_kernel<<<(N_EDGES + 255) / 256, 256>>>(ei);
        cudaStreamWaitEvent(0, g_fork.e2, 0);
    } else {
        prep_kernel<<<prep_blocks, 256>>>(feature, W1);
        gemm_mma_kernel<<<gemm_grid, 256, 2 * STG>>>(b1);
        scatter_kernel<<<(N_EDGES + 255) / 256, 256>>>(ei);
    }

    fusedZ_kernel<<<(N_NODES * 32 + 255) / 256, 256>>>(W2, b2);
    fusedU_kernel<<<(N_NODES * 32 + 255) / 256, 256>>>(scale, out);
}

// round 10
// speedup vs baseline: 1.0373x; 1.0327x over previous
#include <cuda_runtime.h>
#include <cuda_bf16.h>
#include <cuda_fp16.h>
#include <cstdint>

#define N_NODES 10000
#define N_EDGES 320000
#define F_IN 512
#define HID 256
#define M_PAD 10112         // >= 157*64
#define BKT 128

// ---------------- device scratch ----------------
__device__ __align__(16) int   g_pos[N_NODES];                 // zero at load; re-zeroed by fusedU
__device__ __align__(16) int   g_bkt[(size_t)N_NODES * BKT];
__device__ __align__(16) __half g_H0h[(size_t)N_NODES * HID];
__device__ __align__(16) float g_Z[N_NODES * 2];
__device__ __align__(16) __nv_bfloat16 g_Ah[(size_t)M_PAD * F_IN];
__device__ __align__(16) __nv_bfloat16 g_Al[(size_t)M_PAD * F_IN];
__device__ __align__(16) __nv_bfloat16 g_Bh[HID * F_IN];
__device__ __align__(16) __nv_bfloat16 g_Bl[HID * F_IN];

// ---------------- static-init stream/event resources ----------------
struct ForkRes {
    cudaStream_t s = nullptr;
    cudaEvent_t e1 = nullptr, e2 = nullptr;
    bool ok = false;
    ForkRes() {
        if (cudaStreamCreateWithFlags(&s, cudaStreamNonBlocking) == cudaSuccess &&
            cudaEventCreateWithFlags(&e1, cudaEventDisableTiming) == cudaSuccess &&
            cudaEventCreateWithFlags(&e2, cudaEventDisableTiming) == cudaSuccess)
            ok = true;
    }
};
static ForkRes g_fork;

// ---------------- helpers ----------------
#define LDSM_X4(r0, r1, r2, r3, addr) \
    asm volatile("ldmatrix.sync.aligned.m8n8.x4.shared.b16 {%0,%1,%2,%3}, [%4];" \
        : "=r"(r0), "=r"(r1), "=r"(r2), "=r"(r3) : "r"(addr))
#define LDSM_X2(r0, r1, addr) \
    asm volatile("ldmatrix.sync.aligned.m8n8.x2.shared.b16 {%0,%1}, [%2];" \
        : "=r"(r0), "=r"(r1) : "r"(addr))
#define MMA_BF16(d0, d1, d2, d3, a0, a1, a2, a3, b0, b1) \
    asm volatile("mma.sync.aligned.m16n8k16.row.col.f32.bf16.bf16.f32 " \
        "{%0,%1,%2,%3}, {%4,%5,%6,%7}, {%8,%9}, {%0,%1,%2,%3};" \
        : "+f"(d0), "+f"(d1), "+f"(d2), "+f"(d3) \
        : "r"(a0), "r"(a1), "r"(a2), "r"(a3), "r"(b0), "r"(b1))
#define CP16(saddr, gptr) \
    asm volatile("cp.async.cg.shared.global [%0], [%1], 16;" :: "r"(saddr), "l"(gptr))
#define CP_COMMIT() asm volatile("cp.async.commit_group;" ::: "memory")
#define CP_WAIT1()  asm volatile("cp.async.wait_group 1;" ::: "memory")

// ---------------- bucket scatter ----------------
__global__ void scatter_kernel(const int* __restrict__ ei) {
    int e = blockIdx.x * blockDim.x + threadIdx.x;
    if (e >= N_EDGES) return;
    int s = ei[e];
    int d = ei[N_EDGES + e];
    int pos = atomicAdd(&g_pos[d], 1);
    if (pos < BKT) g_bkt[(size_t)d * BKT + pos] = s;
}

// ---------------- prep: bf16-split A + transpose/split W1 ----------------
__global__ void prep_kernel(const float* __restrict__ A, const float* __restrict__ W1) {
    int tid = blockIdx.x * blockDim.x + threadIdx.x;
    if (tid < (N_NODES * F_IN) / 8) {
        int idx8 = tid * 8;
        const float* p = A + idx8;
        float4 v0 = *(const float4*)p;
        float4 v1 = *(const float4*)(p + 4);
        float vals[8] = {v0.x, v0.y, v0.z, v0.w, v1.x, v1.y, v1.z, v1.w};
        uint32_t hw[4], lw[4];
        #pragma unroll
        for (int q = 0; q < 4; q++) {
            __nv_bfloat16 h0 = __float2bfloat16_rn(vals[2 * q]);
            __nv_bfloat16 h1 = __float2bfloat16_rn(vals[2 * q + 1]);
            float r0 = vals[2 * q] - __bfloat162float(h0);
            float r1 = vals[2 * q + 1] - __bfloat162float(h1);
            __nv_bfloat16 l0 = __float2bfloat16_rn(r0);
            __nv_bfloat16 l1 = __float2bfloat16_rn(r1);
            hw[q] = (uint32_t)*(unsigned short*)&h0 | ((uint32_t)*(unsigned short*)&h1 << 16);
            lw[q] = (uint32_t)*(unsigned short*)&l0 | ((uint32_t)*(unsigned short*)&l1 << 16);
        }
        *(uint4*)(g_Ah + idx8) = make_uint4(hw[0], hw[1], hw[2], hw[3]);
        *(uint4*)(g_Al + idx8) = make_uint4(lw[0], lw[1], lw[2], lw[3]);
    }
    if (tid < (F_IN * HID) / 8) {
        int n = tid & 255;
        int kb = (tid >> 8) * 8;
        uint32_t hw[4], lw[4];
        #pragma unroll
        for (int q = 0; q < 4; q++) {
            float x0 = W1[(size_t)(kb + 2 * q) * HID + n];
            float x1 = W1[(size_t)(kb + 2 * q + 1) * HID + n];
            __nv_bfloat16 h0 = __float2bfloat16_rn(x0);
            __nv_bfloat16 h1 = __float2bfloat16_rn(x1);
            float r0 = x0 - __bfloat162float(h0);
            float r1 = x1 - __bfloat162float(h1);
            __nv_bfloat16 l0 = __float2bfloat16_rn(r0);
            __nv_bfloat16 l1 = __float2bfloat16_rn(r1);
            hw[q] = (uint32_t)*(unsigned short*)&h0 | ((uint32_t)*(unsigned short*)&h1 << 16);
            lw[q] = (uint32_t)*(unsigned short*)&l0 | ((uint32_t)*(unsigned short*)&l1 << 16);
        }
        *(uint4*)(g_Bh + (size_t)n * F_IN + kb) = make_uint4(hw[0], hw[1], hw[2], hw[3]);
        *(uint4*)(g_Bl + (size_t)n * F_IN + kb) = make_uint4(lw[0], lw[1], lw[2], lw[3]);
    }
}

// ---------------- HMMA GEMM: CTA tile 64x128, grid (2,157) = 314 CTAs ----------------
// 8 warps (2M x 4N), warp tile 32x32. SMEM/stage: A 64x80 x2 + B 128x80 x2 = 30720B.
#define ROWB 80
#define STG 30720
#define S_AH 0
#define S_AL 5120
#define S_BH 10240
#define S_BL 20480

__global__ __launch_bounds__(256, 2) void gemm_mma_kernel(const float* __restrict__ bias) {
    extern __shared__ __align__(128) char sm[];
    uint32_t sbase = (uint32_t)__cvta_generic_to_shared(sm);

    const int M = N_NODES;
    int tid = threadIdx.x;
    int wid = tid >> 5;
    int lane = tid & 31;
    int wm = wid >> 2;      // 0..1 -> M offset 32*wm
    int wn = wid & 3;       // 0..3 -> N offset 32*wn
    int bm = blockIdx.y * 64;
    int bn = blockIdx.x * 128;

    float acc[2][4][4];
    #pragma unroll
    for (int i = 0; i < 2; i++)
        #pragma unroll
        for (int j = 0; j < 4; j++)
            #pragma unroll
            for (int r = 0; r < 4; r++) acc[i][j][r] = 0.f;

    auto load_stage = [&](int c, int s) {
        int kb = c * 64;                       // byte offset into rows (32 bf16)
        uint32_t sb = sbase + s * STG;
        const char* gA = (const char*)g_Ah + (size_t)bm * 1024 + kb;
        const char* gAl_ = (const char*)g_Al + (size_t)bm * 1024 + kb;
        const char* gB = (const char*)g_Bh + (size_t)bn * 1024 + kb;
        const char* gBl_ = (const char*)g_Bl + (size_t)bn * 1024 + kb;
        // A: 64 rows x 64B = 256 units, 1 per thread
        {
            int r = tid >> 2, j = tid & 3;
            size_t go = (size_t)r * 1024 + j * 16;
            uint32_t so = r * ROWB + j * 16;
            CP16(sb + S_AH + so, gA + go);
            CP16(sb + S_AL + so, gAl_ + go);
        }
        // B: 128 rows x 64B = 512 units, 2 per thread
        #pragma unroll
        for (int i = 0; i < 2; i++) {
            int idx = tid + 256 * i;
            int r = idx >> 2, j = idx & 3;
            size_t go = (size_t)r * 1024 + j * 16;
            uint32_t so = r * ROWB + j * 16;
            CP16(sb + S_BH + so, gB + go);
            CP16(sb + S_BL + so, gBl_ + go);
        }
    };

    load_stage(0, 0);
    CP_COMMIT();

    for (int c = 0; c < 16; c++) {
        int s = c & 1;
        if (c + 1 < 16) load_stage(c + 1, (c + 1) & 1);
        CP_COMMIT();
        CP_WAIT1();
        __syncthreads();

        uint32_t stb = sbase + s * STG;
        #pragma unroll
        for (int ks = 0; ks < 2; ks++) {
            int kbyte = ks * 32;
            uint32_t bh[4][2], bl[4][2];
            #pragma unroll
            for (int na = 0; na < 4; na++) {
                uint32_t ad = stb + S_BH +
                    (uint32_t)((wn * 32 + na * 8 + (lane & 7)) * ROWB + kbyte + ((lane >> 3) & 1) * 16);
                LDSM_X2(bh[na][0], bh[na][1], ad);
                LDSM_X2(bl[na][0], bl[na][1], ad + (S_BL - S_BH));
            }
            #pragma unroll
            for (int ma = 0; ma < 2; ma++) {
                uint32_t aad = stb + S_AH +
                    (uint32_t)((wm * 32 + ma * 16 + (lane & 15)) * ROWB + kbyte + (lane >> 4) * 16);
                uint32_t ah0, ah1, ah2, ah3, al0, al1, al2, al3;
                LDSM_X4(ah0, ah1, ah2, ah3, aad);
                LDSM_X4(al0, al1, al2, al3, aad + (S_AL - S_AH));
                #pragma unroll
                for (int na = 0; na < 4; na++) {
                    MMA_BF16(acc[ma][na][0], acc[ma][na][1], acc[ma][na][2], acc[ma][na][3],
                             ah0, ah1, ah2, ah3, bh[na][0], bh[na][1]);
                    MMA_BF16(acc[ma][na][0], acc[ma][na][1], acc[ma][na][2], acc[ma][na][3],
                             ah0, ah1, ah2, ah3, bl[na][0], bl[na][1]);
                    MMA_BF16(acc[ma][na][0], acc[ma][na][1], acc[ma][na][2], acc[ma][na][3],
                             al0, al1, al2, al3, bh[na][0], bh[na][1]);
                }
            }
        }
        __syncthreads();
    }

    // epilogue: add bias, store fp16
    #pragma unroll
    for (int ma = 0; ma < 2; ma++) {
        int grow0 = bm + wm * 32 + ma * 16 + (lane >> 2);
        int grow1 = grow0 + 8;
        #pragma unroll
        for (int na = 0; na < 4; na++) {
            int col = bn + wn * 32 + na * 8 + (lane & 3) * 2;
            float2 bv = *(const float2*)(bias + col);
            if (grow0 < M) {
                __half2 o = __floats2half2_rn(acc[ma][na][0] + bv.x, acc[ma][na][1] + bv.y);
                *(__half2*)(g_H0h + (size_t)grow0 * HID + col) = o;
            }
            if (grow1 < M) {
                __half2 o = __floats2half2_rn(acc[ma][na][2] + bv.x, acc[ma][na][3] + bv.y);
                *(__half2*)(g_H0h + (size_t)grow1 * HID + col) = o;
            }
        }
    }
}

// ---------------- fusedZ: 2 warps per node, each owns 128 channels ----------------
__global__ __launch_bounds__(256) void fusedZ_kernel(const float* __restrict__ W2,
                                                     const float* __restrict__ b2) {
    __shared__ float sZ[8][2];
    int wid = threadIdx.x >> 5;
    int lane = threadIdx.x & 31;
    int gwarp = blockIdx.x * 8 + wid;
    int node = gwarp >> 1;
    int half = gwarp & 1;
    if (node >= N_NODES) return;

    int cnt = g_pos[node];
    float rdd = rsqrtf(fmaxf((float)cnt, 1.0f));
    if (cnt > BKT) cnt = BKT;
    const int* bkt = g_bkt + (size_t)node * BKT;

    // lane owns channels [half*128 + 4*lane, +4)
    int c0 = half * 128 + 4 * lane;
    float w0[4], w1[4];
    #pragma unroll
    for (int j = 0; j < 4; j++) {
        w0[j] = __ldg(&W2[(c0 + j) * 2 + 0]);
        w1[j] = __ldg(&W2[(c0 + j) * 2 + 1]);
    }
    // byte offset of this lane's 4 fp16 channels within a row
    size_t lane_off = (size_t)half * 128 + 4 * lane;   // element offset

    float acc[4] = {};
    int p = 0;
    for (; p + 4 <= cnt; p += 4) {
        int s0 = bkt[p], s1 = bkt[p + 1], s2 = bkt[p + 2], s3 = bkt[p + 3];
        float n0 = rdd * rsqrtf(fmaxf((float)g_pos[s0], 1.0f));
        float n1 = rdd * rsqrtf(fmaxf((float)g_pos[s1], 1.0f));
        float n2 = rdd * rsqrtf(fmaxf((float)g_pos[s2], 1.0f));
        float n3 = rdd * rsqrtf(fmaxf((float)g_pos[s3], 1.0f));
        uint2 v0 = *(const uint2*)(g_H0h + (size_t)s0 * HID + lane_off);
        uint2 v1 = *(const uint2*)(g_H0h + (size_t)s1 * HID + lane_off);
        uint2 v2 = *(const uint2*)(g_H0h + (size_t)s2 * HID + lane_off);
        uint2 v3 = *(const uint2*)(g_H0h + (size_t)s3 * HID + lane_off);
        float2 f0a = __half22float2(*(const __half2*)&v0.x);
        float2 f0b = __half22float2(*(const __half2*)&v0.y);
        float2 f1a = __half22float2(*(const __half2*)&v1.x);
        float2 f1b = __half22float2(*(const __half2*)&v1.y);
        float2 f2a = __half22float2(*(const __half2*)&v2.x);
        float2 f2b = __half22float2(*(const __half2*)&v2.y);
        float2 f3a = __half22float2(*(const __half2*)&v3.x);
        float2 f3b = __half22float2(*(const __half2*)&v3.y);
        acc[0] += f0a.x * n0 + f1a.x * n1 + f2a.x * n2 + f3a.x * n3;
        acc[1] += f0a.y * n0 + f1a.y * n1 + f2a.y * n2 + f3a.y * n3;
        acc[2] += f0b.x * n0 + f1b.x * n1 + f2b.x * n2 + f3b.x * n3;
        acc[3] += f0b.y * n0 + f1b.y * n1 + f2b.y * n2 + f3b.y * n3;
    }
    for (; p < cnt; p++) {
        int s0 = bkt[p];
        float n0 = rdd * rsqrtf(fmaxf((float)g_pos[s0], 1.0f));
        uint2 v0 = *(const uint2*)(g_H0h + (size_t)s0 * HID + lane_off);
        float2 f0a = __half22float2(*(const __half2*)&v0.x);
        float2 f0b = __half22float2(*(const __half2*)&v0.y);
        acc[0] += f0a.x * n0;
        acc[1] += f0a.y * n0;
        acc[2] += f0b.x * n0;
        acc[3] += f0b.y * n0;
    }

    float z0 = 0.f, z1 = 0.f;
    #pragma unroll
    for (int j = 0; j < 4; j++) {
        float x = fmaxf(acc[j], 0.f);
        z0 += x * w0[j];
        z1 += x * w1[j];
    }
    #pragma unroll
    for (int o = 16; o; o >>= 1) {
        z0 += __shfl_down_sync(0xFFFFFFFFu, z0, o);
        z1 += __shfl_down_sync(0xFFFFFFFFu, z1, o);
    }
    if (lane == 0) {
        sZ[wid][0] = z0;
        sZ[wid][1] = z1;
    }
    __syncthreads();
    if (half == 0 && lane == 0) {
        float t0 = sZ[wid][0] + sZ[wid + 1][0];
        float t1 = sZ[wid][1] + sZ[wid + 1][1];
        g_Z[2 * node + 0] = (t0 + b2[0]) * rdd;
        g_Z[2 * node + 1] = (t1 + b2[1]) * rdd;
    }
}

// ---------------- fusedU + lift + projection; re-zeroes g_pos ----------------
__global__ __launch_bounds__(256) void fusedU_kernel(const float* __restrict__ scale,
                                                     float* __restrict__ out) {
    int gw = (blockIdx.x * blockDim.x + threadIdx.x) >> 5;
    int lane = threadIdx.x & 31;
    if (gw >= N_NODES) return;

    int cnt = g_pos[gw];
    float rdd = rsqrtf(fmaxf((float)cnt, 1.0f));
    if (cnt > BKT) cnt = BKT;
    const int* bkt = g_bkt + (size_t)gw * BKT;
    __syncwarp();
    if (lane == 0) g_pos[gw] = 0;

    float u0 = 0.f, u1 = 0.f;
    for (int p = lane; p < cnt; p += 32) {
        int s = bkt[p];
        float2 z = *(const float2*)(g_Z + 2 * s);
        u0 += z.x;
        u1 += z.y;
    }
    #pragma unroll
    for (int o = 16; o; o >>= 1) {
        u0 += __shfl_down_sync(0xFFFFFFFFu, u0, o);
        u1 += __shfl_down_sync(0xFFFFFFFFu, u1, o);
    }
    if (lane == 0) {
        u0 *= rdd;
        u1 *= rdd;
        float un = sqrtf(u0 * u0 + u1 * u1);
        un = fmaxf(un, 1e-15f);
        float ch = coshf(un);
        float sh = sinhf(un);
        float inv = 1.0f / (un * (1.0f + ch));
        float p0 = sh * u0 * inv;
        float p1 = sh * u1 * inv;
        float pn = fmaxf(sqrtf(p0 * p0 + p1 * p1), 1e-12f);
        const float MIN_SCALE = 2.0f * (0.999f / 3.0f);
        const float MAX_SCALE = 0.999f;
        float s = fminf(fmaxf(scale[0], MIN_SCALE), MAX_SCALE);
        p0 = p0 / pn * s;
        p1 = p1 / pn * s;
        float nrm = fmaxf(sqrtf(p0 * p0 + p1 * p1), 1e-15f);
        float maxnorm = 1.0f - 1e-15f;
        if (nrm > maxnorm) {
            p0 = p0 / nrm * maxnorm;
            p1 = p1 / nrm * maxnorm;
        }
        out[2 * gw + 0] = p0;
        out[2 * gw + 1] = p1;
    }
}

// ---------------- launch ----------------
extern "C" void kernel_launch(void* const* d_in, const int* in_sizes, int n_in,
                              void* d_out, int out_size) {
    const float* feature = (const float*)d_in[0];
    const int* ei = (const int*)d_in[1];
    const float* W1 = (const float*)d_in[2];
    const float* b1 = (const float*)d_in[3];
    const float* W2 = (const float*)d_in[4];
    const float* b2 = (const float*)d_in[5];
    const float* scale = (const float*)d_in[6];
    float* out = (float*)d_out;

    cudaFuncSetAttribute(gemm_mma_kernel,
                         cudaFuncAttributeMaxDynamicSharedMemorySize, 2 * STG);

    dim3 gemm_grid(HID / 128, (N_NODES + 63) / 64);   // (2, 157)
    int prep_blocks = ((N_NODES * F_IN / 8) + 255) / 256;

    if (g_fork.ok) {
        cudaEventRecord(g_fork.e1, 0);
        cudaStreamWaitEvent(g_fork.s, g_fork.e1, 0);
        prep_kernel<<<prep_blocks, 256, 0, g_fork.s>>>(feature, W1);
        gemm_mma_kernel<<<gemm_grid, 256, 2 * STG, g_fork.s>>>(b1);
        cudaEventRecord(g_fork.e2, g_fork.s);

        scatter_kernel<<<(N_EDGES + 255) / 256, 256>>>(ei);
        cudaStreamWaitEvent(0, g_fork.e2, 0);
    } else {
        prep_kernel<<<prep_blocks, 256>>>(feature, W1);
        gemm_mma_kernel<<<gemm_grid, 256, 2 * STG>>>(b1);
        scatter_kernel<<<(N_EDGES + 255) / 256, 256>>>(ei);
    }

    // 2 warps per node -> 20000 warps -> 2500 blocks of 8 warps
    fusedZ_kernel<<<(N_NODES * 2 + 7) / 8, 256>>>(W2, b2);
    fusedU_kernel<<<(N_NODES * 32 + 255) / 256, 256>>>(scale, out);
}

// round 11
// speedup vs baseline: 1.1164x; 1.0763x over previous
#include <cuda_runtime.h>
#include <cuda_bf16.h>
#include <cuda_fp16.h>
#include <cstdint>

#define N_NODES 10000
#define N_EDGES 320000
#define F_IN 512
#define HID 256
#define M_PAD 10112
#define BKT 128

// ---------------- device scratch ----------------
__device__ __align__(16) int   g_pos[N_NODES];                 // zero at load; re-zeroed by fusedU
__device__ __align__(16) int   g_bkt[(size_t)N_NODES * BKT];
__device__ __align__(16) __half g_H0h[(size_t)N_NODES * HID];
__device__ __align__(16) float g_Z[N_NODES * 2];
__device__ __align__(16) __nv_bfloat16 g_Ah[(size_t)M_PAD * F_IN];
__device__ __align__(16) __nv_bfloat16 g_Al[(size_t)M_PAD * F_IN];
__device__ __align__(16) __nv_bfloat16 g_Bh[HID * F_IN];
__device__ __align__(16) __nv_bfloat16 g_Bl[HID * F_IN];

// ---------------- static-init stream/event resources ----------------
struct ForkRes {
    cudaStream_t s = nullptr;
    cudaEvent_t e1 = nullptr, e2 = nullptr;
    bool ok = false;
    ForkRes() {
        if (cudaStreamCreateWithFlags(&s, cudaStreamNonBlocking) == cudaSuccess &&
            cudaEventCreateWithFlags(&e1, cudaEventDisableTiming) == cudaSuccess &&
            cudaEventCreateWithFlags(&e2, cudaEventDisableTiming) == cudaSuccess)
            ok = true;
    }
};
static ForkRes g_fork;

// ---------------- helpers ----------------
#define LDSM_X4(r0, r1, r2, r3, addr) \
    asm volatile("ldmatrix.sync.aligned.m8n8.x4.shared.b16 {%0,%1,%2,%3}, [%4];" \
        : "=r"(r0), "=r"(r1), "=r"(r2), "=r"(r3) : "r"(addr))
#define LDSM_X2(r0, r1, addr) \
    asm volatile("ldmatrix.sync.aligned.m8n8.x2.shared.b16 {%0,%1}, [%2];" \
        : "=r"(r0), "=r"(r1) : "r"(addr))
#define MMA_BF16(d0, d1, d2, d3, a0, a1, a2, a3, b0, b1) \
    asm volatile("mma.sync.aligned.m16n8k16.row.col.f32.bf16.bf16.f32 " \
        "{%0,%1,%2,%3}, {%4,%5,%6,%7}, {%8,%9}, {%0,%1,%2,%3};" \
        : "+f"(d0), "+f"(d1), "+f"(d2), "+f"(d3) \
        : "r"(a0), "r"(a1), "r"(a2), "r"(a3), "r"(b0), "r"(b1))
#define CP16(saddr, gptr) \
    asm volatile("cp.async.cg.shared.global [%0], [%1], 16;" :: "r"(saddr), "l"(gptr))
#define CP_COMMIT() asm volatile("cp.async.commit_group;" ::: "memory")
#define CP_WAIT1()  asm volatile("cp.async.wait_group 1;" ::: "memory")

// ---------------- bucket scatter ----------------
__global__ void scatter_kernel(const int* __restrict__ ei) {
    int e = blockIdx.x * blockDim.x + threadIdx.x;
    if (e >= N_EDGES) return;
    int s = ei[e];
    int d = ei[N_EDGES + e];
    int pos = atomicAdd(&g_pos[d], 1);
    if (pos < BKT) g_bkt[(size_t)d * BKT + pos] = s;
}

// ---------------- prep: bf16-split A + transpose/split W1 ----------------
__global__ void prep_kernel(const float* __restrict__ A, const float* __restrict__ W1) {
    int tid = blockIdx.x * blockDim.x + threadIdx.x;
    if (tid < (N_NODES * F_IN) / 8) {
        int idx8 = tid * 8;
        const float* p = A + idx8;
        float4 v0 = *(const float4*)p;
        float4 v1 = *(const float4*)(p + 4);
        float vals[8] = {v0.x, v0.y, v0.z, v0.w, v1.x, v1.y, v1.z, v1.w};
        uint32_t hw[4], lw[4];
        #pragma unroll
        for (int q = 0; q < 4; q++) {
            __nv_bfloat16 h0 = __float2bfloat16_rn(vals[2 * q]);
            __nv_bfloat16 h1 = __float2bfloat16_rn(vals[2 * q + 1]);
            float r0 = vals[2 * q] - __bfloat162float(h0);
            float r1 = vals[2 * q + 1] - __bfloat162float(h1);
            __nv_bfloat16 l0 = __float2bfloat16_rn(r0);
            __nv_bfloat16 l1 = __float2bfloat16_rn(r1);
            hw[q] = (uint32_t)*(unsigned short*)&h0 | ((uint32_t)*(unsigned short*)&h1 << 16);
            lw[q] = (uint32_t)*(unsigned short*)&l0 | ((uint32_t)*(unsigned short*)&l1 << 16);
        }
        *(uint4*)(g_Ah + idx8) = make_uint4(hw[0], hw[1], hw[2], hw[3]);
        *(uint4*)(g_Al + idx8) = make_uint4(lw[0], lw[1], lw[2], lw[3]);
    }
    if (tid < (F_IN * HID) / 8) {
        int n = tid & 255;
        int kb = (tid >> 8) * 8;
        uint32_t hw[4], lw[4];
        #pragma unroll
        for (int q = 0; q < 4; q++) {
            float x0 = W1[(size_t)(kb + 2 * q) * HID + n];
            float x1 = W1[(size_t)(kb + 2 * q + 1) * HID + n];
            __nv_bfloat16 h0 = __float2bfloat16_rn(x0);
            __nv_bfloat16 h1 = __float2bfloat16_rn(x1);
            float r0 = x0 - __bfloat162float(h0);
            float r1 = x1 - __bfloat162float(h1);
            __nv_bfloat16 l0 = __float2bfloat16_rn(r0);
            __nv_bfloat16 l1 = __float2bfloat16_rn(r1);
            hw[q] = (uint32_t)*(unsigned short*)&h0 | ((uint32_t)*(unsigned short*)&h1 << 16);
            lw[q] = (uint32_t)*(unsigned short*)&l0 | ((uint32_t)*(unsigned short*)&l1 << 16);
        }
        *(uint4*)(g_Bh + (size_t)n * F_IN + kb) = make_uint4(hw[0], hw[1], hw[2], hw[3]);
        *(uint4*)(g_Bl + (size_t)n * F_IN + kb) = make_uint4(lw[0], lw[1], lw[2], lw[3]);
    }
}

// ---------------- HMMA GEMM: CTA tile 64x128, grid (2,157) ----------------
#define ROWB 80
#define STG 30720
#define S_AH 0
#define S_AL 5120
#define S_BH 10240
#define S_BL 20480

__global__ __launch_bounds__(256, 2) void gemm_mma_kernel(const float* __restrict__ bias) {
    extern __shared__ __align__(128) char sm[];
    uint32_t sbase = (uint32_t)__cvta_generic_to_shared(sm);

    const int M = N_NODES;
    int tid = threadIdx.x;
    int wid = tid >> 5;
    int lane = tid & 31;
    int wm = wid >> 2;
    int wn = wid & 3;
    int bm = blockIdx.y * 64;
    int bn = blockIdx.x * 128;

    float acc[2][4][4];
    #pragma unroll
    for (int i = 0; i < 2; i++)
        #pragma unroll
        for (int j = 0; j < 4; j++)
            #pragma unroll
            for (int r = 0; r < 4; r++) acc[i][j][r] = 0.f;

    auto load_stage = [&](int c, int s) {
        int kb = c * 64;
        uint32_t sb = sbase + s * STG;
        const char* gA = (const char*)g_Ah + (size_t)bm * 1024 + kb;
        const char* gAl_ = (const char*)g_Al + (size_t)bm * 1024 + kb;
        const char* gB = (const char*)g_Bh + (size_t)bn * 1024 + kb;
        const char* gBl_ = (const char*)g_Bl + (size_t)bn * 1024 + kb;
        {
            int r = tid >> 2, j = tid & 3;
            size_t go = (size_t)r * 1024 + j * 16;
            uint32_t so = r * ROWB + j * 16;
            CP16(sb + S_AH + so, gA + go);
            CP16(sb + S_AL + so, gAl_ + go);
        }
        #pragma unroll
        for (int i = 0; i < 2; i++) {
            int idx = tid + 256 * i;
            int r = idx >> 2, j = idx & 3;
            size_t go = (size_t)r * 1024 + j * 16;
            uint32_t so = r * ROWB + j * 16;
            CP16(sb + S_BH + so, gB + go);
            CP16(sb + S_BL + so, gBl_ + go);
        }
    };

    load_stage(0, 0);
    CP_COMMIT();

    for (int c = 0; c < 16; c++) {
        int s = c & 1;
        if (c + 1 < 16) load_stage(c + 1, (c + 1) & 1);
        CP_COMMIT();
        CP_WAIT1();
        __syncthreads();

        uint32_t stb = sbase + s * STG;
        #pragma unroll
        for (int ks = 0; ks < 2; ks++) {
            int kbyte = ks * 32;
            uint32_t bh[4][2], bl[4][2];
            #pragma unroll
            for (int na = 0; na < 4; na++) {
                uint32_t ad = stb + S_BH +
                    (uint32_t)((wn * 32 + na * 8 + (lane & 7)) * ROWB + kbyte + ((lane >> 3) & 1) * 16);
                LDSM_X2(bh[na][0], bh[na][1], ad);
                LDSM_X2(bl[na][0], bl[na][1], ad + (S_BL - S_BH));
            }
            #pragma unroll
            for (int ma = 0; ma < 2; ma++) {
                uint32_t aad = stb + S_AH +
                    (uint32_t)((wm * 32 + ma * 16 + (lane & 15)) * ROWB + kbyte + (lane >> 4) * 16);
                uint32_t ah0, ah1, ah2, ah3, al0, al1, al2, al3;
                LDSM_X4(ah0, ah1, ah2, ah3, aad);
                LDSM_X4(al0, al1, al2, al3, aad + (S_AL - S_AH));
                #pragma unroll
                for (int na = 0; na < 4; na++) {
                    MMA_BF16(acc[ma][na][0], acc[ma][na][1], acc[ma][na][2], acc[ma][na][3],
                             ah0, ah1, ah2, ah3, bh[na][0], bh[na][1]);
                    MMA_BF16(acc[ma][na][0], acc[ma][na][1], acc[ma][na][2], acc[ma][na][3],
                             ah0, ah1, ah2, ah3, bl[na][0], bl[na][1]);
                    MMA_BF16(acc[ma][na][0], acc[ma][na][1], acc[ma][na][2], acc[ma][na][3],
                             al0, al1, al2, al3, bh[na][0], bh[na][1]);
                }
            }
        }
        __syncthreads();
    }

    #pragma unroll
    for (int ma = 0; ma < 2; ma++) {
        int grow0 = bm + wm * 32 + ma * 16 + (lane >> 2);
        int grow1 = grow0 + 8;
        #pragma unroll
        for (int na = 0; na < 4; na++) {
            int col = bn + wn * 32 + na * 8 + (lane & 3) * 2;
            float2 bv = *(const float2*)(bias + col);
            if (grow0 < M) {
                __half2 o = __floats2half2_rn(acc[ma][na][0] + bv.x, acc[ma][na][1] + bv.y);
                *(__half2*)(g_H0h + (size_t)grow0 * HID + col) = o;
            }
            if (grow1 < M) {
                __half2 o = __floats2half2_rn(acc[ma][na][2] + bv.x, acc[ma][na][3] + bv.y);
                *(__half2*)(g_H0h + (size_t)grow1 * HID + col) = o;
            }
        }
    }
}

// ---------------- prescale: H0[row] *= rdeg[row] (in place, fp32 math) ----------------
__global__ void prescale_kernel() {
    int t = blockIdx.x * blockDim.x + threadIdx.x;
    if (t >= N_NODES * HID / 8) return;
    int row = t >> 5;                 // 32 uint4 per row
    int off = (t & 31) * 8;
    float r = rsqrtf(fmaxf((float)g_pos[row], 1.0f));
    uint4 v = *(uint4*)(g_H0h + (size_t)row * HID + off);
    __half2* h = (__half2*)&v;
    #pragma unroll
    for (int q = 0; q < 4; q++) {
        float2 f = __half22float2(h[q]);
        h[q] = __floats2half2_rn(f.x * r, f.y * r);
    }
    *(uint4*)(g_H0h + (size_t)row * HID + off) = v;
}

// ---------------- fusedZ: 2 warps per node; H0 pre-scaled -> pure adds ----------------
__global__ __launch_bounds__(256) void fusedZ_kernel(const float* __restrict__ W2,
                                                     const float* __restrict__ b2) {
    __shared__ float sZ[8][2];
    int wid = threadIdx.x >> 5;
    int lane = threadIdx.x & 31;
    int gwarp = blockIdx.x * 8 + wid;
    int node = gwarp >> 1;
    int half = gwarp & 1;
    if (node >= N_NODES) return;

    int cnt = g_pos[node];
    float rdd = rsqrtf(fmaxf((float)cnt, 1.0f));
    if (cnt > BKT) cnt = BKT;
    const int* bkt = g_bkt + (size_t)node * BKT;

    int c0 = half * 128 + 4 * lane;
    float w0[4], w1[4];
    #pragma unroll
    for (int j = 0; j < 4; j++) {
        w0[j] = __ldg(&W2[(c0 + j) * 2 + 0]);
        w1[j] = __ldg(&W2[(c0 + j) * 2 + 1]);
    }
    size_t lane_off = (size_t)half * 128 + 4 * lane;

    float acc[4] = {};
    int p = 0;
    for (; p + 4 <= cnt; p += 4) {
        int s0 = bkt[p], s1 = bkt[p + 1], s2 = bkt[p + 2], s3 = bkt[p + 3];
        uint2 v0 = *(const uint2*)(g_H0h + (size_t)s0 * HID + lane_off);
        uint2 v1 = *(const uint2*)(g_H0h + (size_t)s1 * HID + lane_off);
        uint2 v2 = *(const uint2*)(g_H0h + (size_t)s2 * HID + lane_off);
        uint2 v3 = *(const uint2*)(g_H0h + (size_t)s3 * HID + lane_off);
        float2 f0a = __half22float2(*(const __half2*)&v0.x);
        float2 f0b = __half22float2(*(const __half2*)&v0.y);
        float2 f1a = __half22float2(*(const __half2*)&v1.x);
        float2 f1b = __half22float2(*(const __half2*)&v1.y);
        float2 f2a = __half22float2(*(const __half2*)&v2.x);
        float2 f2b = __half22float2(*(const __half2*)&v2.y);
        float2 f3a = __half22float2(*(const __half2*)&v3.x);
        float2 f3b = __half22float2(*(const __half2*)&v3.y);
        acc[0] += (f0a.x + f1a.x) + (f2a.x + f3a.x);
        acc[1] += (f0a.y + f1a.y) + (f2a.y + f3a.y);
        acc[2] += (f0b.x + f1b.x) + (f2b.x + f3b.x);
        acc[3] += (f0b.y + f1b.y) + (f2b.y + f3b.y);
    }
    for (; p < cnt; p++) {
        int s0 = bkt[p];
        uint2 v0 = *(const uint2*)(g_H0h + (size_t)s0 * HID + lane_off);
        float2 f0a = __half22float2(*(const __half2*)&v0.x);
        float2 f0b = __half22float2(*(const __half2*)&v0.y);
        acc[0] += f0a.x;
        acc[1] += f0a.y;
        acc[2] += f0b.x;
        acc[3] += f0b.y;
    }

    float z0 = 0.f, z1 = 0.f;
    #pragma unroll
    for (int j = 0; j < 4; j++) {
        float x = fmaxf(acc[j] * rdd, 0.f);   // AGG1 = rdd * sum(prescaled rows)
        z0 += x * w0[j];
        z1 += x * w1[j];
    }
    #pragma unroll
    for (int o = 16; o; o >>= 1) {
        z0 += __shfl_down_sync(0xFFFFFFFFu, z0, o);
        z1 += __shfl_down_sync(0xFFFFFFFFu, z1, o);
    }
    if (lane == 0) {
        sZ[wid][0] = z0;
        sZ[wid][1] = z1;
    }
    __syncthreads();
    if (half == 0 && lane == 0) {
        float t0 = sZ[wid][0] + sZ[wid + 1][0];
        float t1 = sZ[wid][1] + sZ[wid + 1][1];
        g_Z[2 * node + 0] = (t0 + b2[0]) * rdd;   // pre-scale for layer-2 source role
        g_Z[2 * node + 1] = (t1 + b2[1]) * rdd;
    }
}

// ---------------- fusedU + lift + projection; re-zeroes g_pos ----------------
__global__ __launch_bounds__(256) void fusedU_kernel(const float* __restrict__ scale,
                                                     float* __restrict__ out) {
    int gw = (blockIdx.x * blockDim.x + threadIdx.x) >> 5;
    int lane = threadIdx.x & 31;
    if (gw >= N_NODES) return;

    int cnt = g_pos[gw];
    float rdd = rsqrtf(fmaxf((float)cnt, 1.0f));
    if (cnt > BKT) cnt = BKT;
    const int* bkt = g_bkt + (size_t)gw * BKT;
    __syncwarp();
    if (lane == 0) g_pos[gw] = 0;

    float u0 = 0.f, u1 = 0.f;
    for (int p = lane; p < cnt; p += 32) {
        int s = bkt[p];
        float2 z = *(const float2*)(g_Z + 2 * s);
        u0 += z.x;
        u1 += z.y;
    }
    #pragma unroll
    for (int o = 16; o; o >>= 1) {
        u0 += __shfl_down_sync(0xFFFFFFFFu, u0, o);
        u1 += __shfl_down_sync(0xFFFFFFFFu, u1, o);
    }
    if (lane == 0) {
        u0 *= rdd;
        u1 *= rdd;
        float un = sqrtf(u0 * u0 + u1 * u1);
        un = fmaxf(un, 1e-15f);
        float ch = coshf(un);
        float sh = sinhf(un);
        float inv = 1.0f / (un * (1.0f + ch));
        float p0 = sh * u0 * inv;
        float p1 = sh * u1 * inv;
        float pn = fmaxf(sqrtf(p0 * p0 + p1 * p1), 1e-12f);
        const float MIN_SCALE = 2.0f * (0.999f / 3.0f);
        const float MAX_SCALE = 0.999f;
        float s = fminf(fmaxf(scale[0], MIN_SCALE), MAX_SCALE);
        p0 = p0 / pn * s;
        p1 = p1 / pn * s;
        float nrm = fmaxf(sqrtf(p0 * p0 + p1 * p1), 1e-15f);
        float maxnorm = 1.0f - 1e-15f;
        if (nrm > maxnorm) {
            p0 = p0 / nrm * maxnorm;
            p1 = p1 / nrm * maxnorm;
        }
        out[2 * gw + 0] = p0;
        out[2 * gw + 1] = p1;
    }
}

// ---------------- launch ----------------
extern "C" void kernel_launch(void* const* d_in, const int* in_sizes, int n_in,
                              void* d_out, int out_size) {
    const float* feature = (const float*)d_in[0];
    const int* ei = (const int*)d_in[1];
    const float* W1 = (const float*)d_in[2];
    const float* b1 = (const float*)d_in[3];
    const float* W2 = (const float*)d_in[4];
    const float* b2 = (const float*)d_in[5];
    const float* scale = (const float*)d_in[6];
    float* out = (float*)d_out;

    cudaFuncSetAttribute(gemm_mma_kernel,
                         cudaFuncAttributeMaxDynamicSharedMemorySize, 2 * STG);

    dim3 gemm_grid(HID / 128, (N_NODES + 63) / 64);   // (2, 157)
    int prep_blocks = ((N_NODES * F_IN / 8) + 255) / 256;

    if (g_fork.ok) {
        cudaEventRecord(g_fork.e1, 0);
        cudaStreamWaitEvent(g_fork.s, g_fork.e1, 0);
        prep_kernel<<<prep_blocks, 256, 0, g_fork.s>>>(feature, W1);
        gemm_mma_kernel<<<gemm_grid, 256, 2 * STG, g_fork.s>>>(b1);
        cudaEventRecord(g_fork.e2, g_fork.s);

        scatter_kernel<<<(N_EDGES + 255) / 256, 256>>>(ei);
        cudaStreamWaitEvent(0, g_fork.e2, 0);
    } else {
        prep_kernel<<<prep_blocks, 256>>>(feature, W1);
        gemm_mma_kernel<<<gemm_grid, 256, 2 * STG>>>(b1);
        scatter_kernel<<<(N_EDGES + 255) / 256, 256>>>(ei);
    }

    prescale_kernel<<<(N_NODES * HID / 8 + 255) / 256, 256>>>();
    fusedZ_kernel<<<(N_NODES * 2 + 7) / 8, 256>>>(W2, b2);
    fusedU_kernel<<<(N_NODES * 32 + 255) / 256, 256>>>(scale, out);
}

// round 12
// speedup vs baseline: 1.4635x; 1.3108x over previous
#include <cuda_runtime.h>
#include <cuda_fp16.h>
#include <cstdint>

#define N_NODES 10000
#define N_EDGES 320000
#define F_IN 512
#define HID 256
#define M_PAD 10112
#define BKT 128

// ---------------- device scratch ----------------
__device__ __align__(16) int   g_pos[N_NODES];                 // zero at load; re-zeroed by fusedU
__device__ __align__(16) int   g_bkt[(size_t)N_NODES * BKT];
__device__ __align__(16) __half g_H0h[(size_t)N_NODES * HID];  // (H0+b1)*rdeg, fp16
__device__ __align__(16) float g_Z[N_NODES * 2];
__device__ __align__(16) __half g_Af[(size_t)M_PAD * F_IN];    // feature fp16
__device__ __align__(16) __half g_Bf[HID * F_IN];              // W1^T fp16 [n][k]

// ---------------- static-init stream/event resources ----------------
struct ForkRes {
    cudaStream_t s = nullptr;
    cudaEvent_t e1 = nullptr, e2 = nullptr, e3 = nullptr;
    bool ok = false;
    ForkRes() {
        if (cudaStreamCreateWithFlags(&s, cudaStreamNonBlocking) == cudaSuccess &&
            cudaEventCreateWithFlags(&e1, cudaEventDisableTiming) == cudaSuccess &&
            cudaEventCreateWithFlags(&e2, cudaEventDisableTiming) == cudaSuccess &&
            cudaEventCreateWithFlags(&e3, cudaEventDisableTiming) == cudaSuccess)
            ok = true;
    }
};
static ForkRes g_fork;

// ---------------- helpers ----------------
#define LDSM_X4(r0, r1, r2, r3, addr) \
    asm volatile("ldmatrix.sync.aligned.m8n8.x4.shared.b16 {%0,%1,%2,%3}, [%4];" \
        : "=r"(r0), "=r"(r1), "=r"(r2), "=r"(r3) : "r"(addr))
#define LDSM_X2(r0, r1, addr) \
    asm volatile("ldmatrix.sync.aligned.m8n8.x2.shared.b16 {%0,%1}, [%2];" \
        : "=r"(r0), "=r"(r1) : "r"(addr))
#define MMA_F16(d0, d1, d2, d3, a0, a1, a2, a3, b0, b1) \
    asm volatile("mma.sync.aligned.m16n8k16.row.col.f32.f16.f16.f32 " \
        "{%0,%1,%2,%3}, {%4,%5,%6,%7}, {%8,%9}, {%0,%1,%2,%3};" \
        : "+f"(d0), "+f"(d1), "+f"(d2), "+f"(d3) \
        : "r"(a0), "r"(a1), "r"(a2), "r"(a3), "r"(b0), "r"(b1))
#define CP16(saddr, gptr) \
    asm volatile("cp.async.cg.shared.global [%0], [%1], 16;" :: "r"(saddr), "l"(gptr))
#define CP_COMMIT() asm volatile("cp.async.commit_group;" ::: "memory")
#define CP_WAIT1()  asm volatile("cp.async.wait_group 1;" ::: "memory")

// ---------------- bucket scatter ----------------
__global__ void scatter_kernel(const int* __restrict__ ei) {
    int e = blockIdx.x * blockDim.x + threadIdx.x;
    if (e >= N_EDGES) return;
    int s = ei[e];
    int d = ei[N_EDGES + e];
    int pos = atomicAdd(&g_pos[d], 1);
    if (pos < BKT) g_bkt[(size_t)d * BKT + pos] = s;
}

// ---------------- prep: fp16 A + transpose fp16 W1 ----------------
__global__ void prep_kernel(const float* __restrict__ A, const float* __restrict__ W1) {
    int tid = blockIdx.x * blockDim.x + threadIdx.x;
    if (tid < (N_NODES * F_IN) / 8) {
        int idx8 = tid * 8;
        const float* p = A + idx8;
        float4 v0 = *(const float4*)p;
        float4 v1 = *(const float4*)(p + 4);
        uint32_t w[4];
        __half2 h;
        h = __floats2half2_rn(v0.x, v0.y); w[0] = *(uint32_t*)&h;
        h = __floats2half2_rn(v0.z, v0.w); w[1] = *(uint32_t*)&h;
        h = __floats2half2_rn(v1.x, v1.y); w[2] = *(uint32_t*)&h;
        h = __floats2half2_rn(v1.z, v1.w); w[3] = *(uint32_t*)&h;
        *(uint4*)(g_Af + idx8) = make_uint4(w[0], w[1], w[2], w[3]);
    }
    if (tid < (F_IN * HID) / 8) {
        int n = tid & 255;
        int kb = (tid >> 8) * 8;
        uint32_t w[4];
        #pragma unroll
        for (int q = 0; q < 4; q++) {
            float x0 = W1[(size_t)(kb + 2 * q) * HID + n];
            float x1 = W1[(size_t)(kb + 2 * q + 1) * HID + n];
            __half2 h = __floats2half2_rn(x0, x1);
            w[q] = *(uint32_t*)&h;
        }
        *(uint4*)(g_Bf + (size_t)n * F_IN + kb) = make_uint4(w[0], w[1], w[2], w[3]);
    }
}

// ---------------- HMMA fp16 GEMM: CTA tile 64x128, grid (2,157) ----------------
// Epilogue: H0h[row] = (acc + bias) * rsqrt(max(deg,1))   (prescale folded in)
#define ROWB 80
#define S_A 0
#define S_B 5120
#define STG 15360

__global__ __launch_bounds__(256, 2) void gemm_mma_kernel(const float* __restrict__ bias) {
    extern __shared__ __align__(128) char sm[];
    uint32_t sbase = (uint32_t)__cvta_generic_to_shared(sm);

    const int M = N_NODES;
    int tid = threadIdx.x;
    int wid = tid >> 5;
    int lane = tid & 31;
    int wm = wid >> 2;
    int wn = wid & 3;
    int bm = blockIdx.y * 64;
    int bn = blockIdx.x * 128;

    float acc[2][4][4];
    #pragma unroll
    for (int i = 0; i < 2; i++)
        #pragma unroll
        for (int j = 0; j < 4; j++)
            #pragma unroll
            for (int r = 0; r < 4; r++) acc[i][j][r] = 0.f;

    auto load_stage = [&](int c, int s) {
        int kb = c * 64;
        uint32_t sb = sbase + s * STG;
        const char* gA = (const char*)g_Af + (size_t)bm * 1024 + kb;
        const char* gB = (const char*)g_Bf + (size_t)bn * 1024 + kb;
        {
            int r = tid >> 2, j = tid & 3;
            CP16(sb + S_A + r * ROWB + j * 16, gA + (size_t)r * 1024 + j * 16);
        }
        #pragma unroll
        for (int i = 0; i < 2; i++) {
            int idx = tid + 256 * i;
            int r = idx >> 2, j = idx & 3;
            CP16(sb + S_B + r * ROWB + j * 16, gB + (size_t)r * 1024 + j * 16);
        }
    };

    load_stage(0, 0);
    CP_COMMIT();

    for (int c = 0; c < 16; c++) {
        int s = c & 1;
        if (c + 1 < 16) load_stage(c + 1, (c + 1) & 1);
        CP_COMMIT();
        CP_WAIT1();
        __syncthreads();

        uint32_t stb = sbase + s * STG;
        #pragma unroll
        for (int ks = 0; ks < 2; ks++) {
            int kbyte = ks * 32;
            uint32_t bf[4][2];
            #pragma unroll
            for (int na = 0; na < 4; na++) {
                uint32_t ad = stb + S_B +
                    (uint32_t)((wn * 32 + na * 8 + (lane & 7)) * ROWB + kbyte + ((lane >> 3) & 1) * 16);
                LDSM_X2(bf[na][0], bf[na][1], ad);
            }
            #pragma unroll
            for (int ma = 0; ma < 2; ma++) {
                uint32_t aad = stb + S_A +
                    (uint32_t)((wm * 32 + ma * 16 + (lane & 15)) * ROWB + kbyte + (lane >> 4) * 16);
                uint32_t a0, a1, a2, a3;
                LDSM_X4(a0, a1, a2, a3, aad);
                #pragma unroll
                for (int na = 0; na < 4; na++) {
                    MMA_F16(acc[ma][na][0], acc[ma][na][1], acc[ma][na][2], acc[ma][na][3],
                            a0, a1, a2, a3, bf[na][0], bf[na][1]);
                }
            }
        }
        __syncthreads();
    }

    // epilogue: (acc + bias) * rdeg[row], store fp16
    #pragma unroll
    for (int ma = 0; ma < 2; ma++) {
        int grow0 = bm + wm * 32 + ma * 16 + (lane >> 2);
        int grow1 = grow0 + 8;
        float r0 = (grow0 < M) ? rsqrtf(fmaxf((float)g_pos[grow0], 1.0f)) : 0.f;
        float r1 = (grow1 < M) ? rsqrtf(fmaxf((float)g_pos[grow1], 1.0f)) : 0.f;
        #pragma unroll
        for (int na = 0; na < 4; na++) {
            int col = bn + wn * 32 + na * 8 + (lane & 3) * 2;
            float2 bv = *(const float2*)(bias + col);
            if (grow0 < M) {
                __half2 o = __floats2half2_rn((acc[ma][na][0] + bv.x) * r0,
                                              (acc[ma][na][1] + bv.y) * r0);
                *(__half2*)(g_H0h + (size_t)grow0 * HID + col) = o;
            }
            if (grow1 < M) {
                __half2 o = __floats2half2_rn((acc[ma][na][2] + bv.x) * r1,
                                              (acc[ma][na][3] + bv.y) * r1);
                *(__half2*)(g_H0h + (size_t)grow1 * HID + col) = o;
            }
        }
    }
}

// ---------------- fusedZ: 2 warps per node; H0 pre-scaled -> pure adds ----------------
__global__ __launch_bounds__(256) void fusedZ_kernel(const float* __restrict__ W2,
                                                     const float* __restrict__ b2) {
    __shared__ float sZ[8][2];
    int wid = threadIdx.x >> 5;
    int lane = threadIdx.x & 31;
    int gwarp = blockIdx.x * 8 + wid;
    int node = gwarp >> 1;
    int half = gwarp & 1;
    if (node >= N_NODES) return;

    int cnt = g_pos[node];
    float rdd = rsqrtf(fmaxf((float)cnt, 1.0f));
    if (cnt > BKT) cnt = BKT;
    const int* bkt = g_bkt + (size_t)node * BKT;

    int c0 = half * 128 + 4 * lane;
    float w0[4], w1[4];
    #pragma unroll
    for (int j = 0; j < 4; j++) {
        w0[j] = __ldg(&W2[(c0 + j) * 2 + 0]);
        w1[j] = __ldg(&W2[(c0 + j) * 2 + 1]);
    }
    size_t lane_off = (size_t)half * 128 + 4 * lane;

    float acc[4] = {};
    int p = 0;
    for (; p + 4 <= cnt; p += 4) {
        uint4 idx = *(const uint4*)(bkt + p);
        uint2 v0 = *(const uint2*)(g_H0h + (size_t)idx.x * HID + lane_off);
        uint2 v1 = *(const uint2*)(g_H0h + (size_t)idx.y * HID + lane_off);
        uint2 v2 = *(const uint2*)(g_H0h + (size_t)idx.z * HID + lane_off);
        uint2 v3 = *(const uint2*)(g_H0h + (size_t)idx.w * HID + lane_off);
        float2 f0a = __half22float2(*(const __half2*)&v0.x);
        float2 f0b = __half22float2(*(const __half2*)&v0.y);
        float2 f1a = __half22float2(*(const __half2*)&v1.x);
        float2 f1b = __half22float2(*(const __half2*)&v1.y);
        float2 f2a = __half22float2(*(const __half2*)&v2.x);
        float2 f2b = __half22float2(*(const __half2*)&v2.y);
        float2 f3a = __half22float2(*(const __half2*)&v3.x);
        float2 f3b = __half22float2(*(const __half2*)&v3.y);
        acc[0] += (f0a.x + f1a.x) + (f2a.x + f3a.x);
        acc[1] += (f0a.y + f1a.y) + (f2a.y + f3a.y);
        acc[2] += (f0b.x + f1b.x) + (f2b.x + f3b.x);
        acc[3] += (f0b.y + f1b.y) + (f2b.y + f3b.y);
    }
    for (; p < cnt; p++) {
        int s0 = bkt[p];
        uint2 v0 = *(const uint2*)(g_H0h + (size_t)s0 * HID + lane_off);
        float2 f0a = __half22float2(*(const __half2*)&v0.x);
        float2 f0b = __half22float2(*(const __half2*)&v0.y);
        acc[0] += f0a.x;
        acc[1] += f0a.y;
        acc[2] += f0b.x;
        acc[3] += f0b.y;
    }

    float z0 = 0.f, z1 = 0.f;
    #pragma unroll
    for (int j = 0; j < 4; j++) {
        float x = fmaxf(acc[j] * rdd, 0.f);
        z0 += x * w0[j];
        z1 += x * w1[j];
    }
    #pragma unroll
    for (int o = 16; o; o >>= 1) {
        z0 += __shfl_down_sync(0xFFFFFFFFu, z0, o);
        z1 += __shfl_down_sync(0xFFFFFFFFu, z1, o);
    }
    if (lane == 0) {
        sZ[wid][0] = z0;
        sZ[wid][1] = z1;
    }
    __syncthreads();
    if (half == 0 && lane == 0) {
        float t0 = sZ[wid][0] + sZ[wid + 1][0];
        float t1 = sZ[wid][1] + sZ[wid + 1][1];
        g_Z[2 * node + 0] = (t0 + b2[0]) * rdd;   // pre-scale for layer-2 source role
        g_Z[2 * node + 1] = (t1 + b2[1]) * rdd;
    }
}

// ---------------- fusedU + lift + projection; re-zeroes g_pos ----------------
__global__ __launch_bounds__(256) void fusedU_kernel(const float* __restrict__ scale,
                                                     float* __restrict__ out) {
    int gw = (blockIdx.x * blockDim.x + threadIdx.x) >> 5;
    int lane = threadIdx.x & 31;
    if (gw >= N_NODES) return;

    int cnt = g_pos[gw];
    float rdd = rsqrtf(fmaxf((float)cnt, 1.0f));
    if (cnt > BKT) cnt = BKT;
    const int* bkt = g_bkt + (size_t)gw * BKT;
    __syncwarp();
    if (lane == 0) g_pos[gw] = 0;

    float u0 = 0.f, u1 = 0.f;
    for (int p = lane; p < cnt; p += 32) {
        int s = bkt[p];
        float2 z = *(const float2*)(g_Z + 2 * s);
        u0 += z.x;
        u1 += z.y;
    }
    #pragma unroll
    for (int o = 16; o; o >>= 1) {
        u0 += __shfl_down_sync(0xFFFFFFFFu, u0, o);
        u1 += __shfl_down_sync(0xFFFFFFFFu, u1, o);
    }
    if (lane == 0) {
        u0 *= rdd;
        u1 *= rdd;
        float un = sqrtf(u0 * u0 + u1 * u1);
        un = fmaxf(un, 1e-15f);
        float ch = coshf(un);
        float sh = sinhf(un);
        float inv = 1.0f / (un * (1.0f + ch));
        float p0 = sh * u0 * inv;
        float p1 = sh * u1 * inv;
        float pn = fmaxf(sqrtf(p0 * p0 + p1 * p1), 1e-12f);
        const float MIN_SCALE = 2.0f * (0.999f / 3.0f);
        const float MAX_SCALE = 0.999f;
        float s = fminf(fmaxf(scale[0], MIN_SCALE), MAX_SCALE);
        p0 = p0 / pn * s;
        p1 = p1 / pn * s;
        float nrm = fmaxf(sqrtf(p0 * p0 + p1 * p1), 1e-15f);
        float maxnorm = 1.0f - 1e-15f;
        if (nrm > maxnorm) {
            p0 = p0 / nrm * maxnorm;
            p1 = p1 / nrm * maxnorm;
        }
        out[2 * gw + 0] = p0;
        out[2 * gw + 1] = p1;
    }
}

// ---------------- launch ----------------
extern "C" void kernel_launch(void* const* d_in, const int* in_sizes, int n_in,
                              void* d_out, int out_size) {
    const float* feature = (const float*)d_in[0];
    const int* ei = (const int*)d_in[1];
    const float* W1 = (const float*)d_in[2];
    const float* b1 = (const float*)d_in[3];
    const float* W2 = (const float*)d_in[4];
    const float* b2 = (const float*)d_in[5];
    const float* scale = (const float*)d_in[6];
    float* out = (float*)d_out;

    cudaFuncSetAttribute(gemm_mma_kernel,
                         cudaFuncAttributeMaxDynamicSharedMemorySize, 2 * STG);

    dim3 gemm_grid(HID / 128, (N_NODES + 63) / 64);   // (2, 157)
    int prep_blocks = ((N_NODES * F_IN / 8) + 255) / 256;

    if (g_fork.ok) {
        // fork: prep on side stream in parallel with scatter on main stream;
        // gemm (needs g_pos for the folded prescale) waits for scatter.
        cudaEventRecord(g_fork.e1, 0);
        cudaStreamWaitEvent(g_fork.s, g_fork.e1, 0);
        prep_kernel<<<prep_blocks, 256, 0, g_fork.s>>>(feature, W1);

        scatter_kernel<<<(N_EDGES + 255) / 256, 256>>>(ei);
        cudaEventRecord(g_fork.e3, 0);
        cudaStreamWaitEvent(g_fork.s, g_fork.e3, 0);

        gemm_mma_kernel<<<gemm_grid, 256, 2 * STG, g_fork.s>>>(b1);
        cudaEventRecord(g_fork.e2, g_fork.s);
        cudaStreamWaitEvent(0, g_fork.e2, 0);
    } else {
        prep_kernel<<<prep_blocks, 256>>>(feature, W1);
        scatter_kernel<<<(N_EDGES + 255) / 256, 256>>>(ei);
        gemm_mma_kernel<<<gemm_grid, 256, 2 * STG>>>(b1);
    }

    fusedZ_kernel<<<(N_NODES * 2 + 7) / 8, 256>>>(W2, b2);
    fusedU_kernel<<<(N_NODES * 32 + 255) / 256, 256>>>(scale, out);
}